// round 8
// baseline (speedup 1.0000x reference)
#include <cuda_runtime.h>
#include <cuda_fp16.h>
#include <cstdint>

// ---------------------------------------------------------------------------
// Problem constants
// ---------------------------------------------------------------------------
#define M_TOTAL 8192
#define N_TOTAL 16384
#define K_TOTAL 4096

#define BM 128
#define BN 128
#define BK 64                          // fp16 elems per K chunk (128 B rows)
#define NCHUNK (K_TOTAL / BK)          // 64
#define STAGES 3
#define A_BYTES 16384u                 // 128 rows * 128 B
#define STAGE_BYTES (2u * A_BYTES)     // A + B = 32768
#define SMEM_GEMM (STAGES * STAGE_BYTES)       // 98304 -> 2 CTAs/SM

// fp16 staging buffers (allocation-free scratch: __device__ globals)
__device__ __half g_x16[(size_t)M_TOTAL * K_TOTAL];   // 64 MB
__device__ __half g_w16[(size_t)N_TOTAL * K_TOTAL];   // 128 MB
__device__ int g_w_is_i32;             // weight dtype flag (detect kernel)

// ---------------------------------------------------------------------------
// Helpers
// ---------------------------------------------------------------------------
__device__ __forceinline__ uint32_t smem_u32(const void* p) {
    uint32_t r;
    asm("{ .reg .u64 t; cvta.to.shared.u64 t, %1; cvt.u32.u64 %0, t; }"
        : "=r"(r) : "l"(p));
    return r;
}

// Classic 128-byte-row swizzle: bits[6:4] ^= bits[9:7]. XOR-linear.
#define SWZ128(o) ((o) ^ (((o) >> 3) & 0x70))

__device__ __forceinline__ void cp_async16(uint32_t dst, const void* src) {
    asm volatile("cp.async.cg.shared.global [%0], [%1], 16;\n"
                 :: "r"(dst), "l"(src));
}
#define CP_COMMIT() asm volatile("cp.async.commit_group;\n" ::: "memory")
#define CP_WAIT(n)  asm volatile("cp.async.wait_group %0;\n" :: "n"(n) : "memory")

__device__ __forceinline__ void ldsm_x4(uint32_t& r0, uint32_t& r1,
                                        uint32_t& r2, uint32_t& r3,
                                        uint32_t addr) {
    asm volatile("ldmatrix.sync.aligned.m8n8.x4.shared.b16 {%0,%1,%2,%3}, [%4];"
                 : "=r"(r0), "=r"(r1), "=r"(r2), "=r"(r3) : "r"(addr));
}

__device__ __forceinline__ void mma16816(float* d, const uint32_t* a,
                                         const uint32_t* b) {
    asm volatile(
        "mma.sync.aligned.m16n8k16.row.col.f32.f16.f16.f32 "
        "{%0,%1,%2,%3}, {%4,%5,%6,%7}, {%8,%9}, {%0,%1,%2,%3};"
        : "+f"(d[0]), "+f"(d[1]), "+f"(d[2]), "+f"(d[3])
        : "r"(a[0]), "r"(a[1]), "r"(a[2]), "r"(a[3]), "r"(b[0]), "r"(b[1]));
}

// ---------------------------------------------------------------------------
// Weight dtype detection (int8 bytes read as int32 words land in [-127,127]
// with prob ~2^-24/word; all 16384 words in range <=> int32 buffer).
// ---------------------------------------------------------------------------
__global__ void __launch_bounds__(256) detect_w_kernel(const int4* __restrict__ w) {
    __shared__ int s_out_of_range;
    if (threadIdx.x == 0) s_out_of_range = 0;
    __syncthreads();
    int bad = 0;
#pragma unroll
    for (int it = 0; it < 16; it++) {
        int4 v = w[threadIdx.x * 16 + it];
        if (v.x < -127 || v.x > 127 || v.y < -127 || v.y > 127 ||
            v.z < -127 || v.z > 127 || v.w < -127 || v.w > 127) bad = 1;
    }
    if (bad) atomicOr(&s_out_of_range, 1);
    __syncthreads();
    if (threadIdx.x == 0) g_w_is_i32 = s_out_of_range ? 0 : 1;
}

// ---------------------------------------------------------------------------
// Conversion kernels
// ---------------------------------------------------------------------------
__global__ void __launch_bounds__(256) cvt_x_kernel(const float4* __restrict__ x) {
    size_t i = (size_t)blockIdx.x * blockDim.x + threadIdx.x;
    float4 v = x[i];
    __half2 a = __floats2half2_rn(v.x, v.y);
    __half2 b = __floats2half2_rn(v.z, v.w);
    reinterpret_cast<uint2*>(g_x16)[i] =
        make_uint2(*reinterpret_cast<uint32_t*>(&a),
                   *reinterpret_cast<uint32_t*>(&b));
}

__global__ void __launch_bounds__(256) cvt_w_kernel(const void* __restrict__ wraw) {
    size_t i = (size_t)blockIdx.x * blockDim.x + threadIdx.x;
    uint32_t o[4];
    if (g_w_is_i32) {
        const int4* w = (const int4*)wraw;
        int4 v0 = w[2 * i];
        int4 v1 = w[2 * i + 1];
        __half2 h0 = __floats2half2_rn((float)v0.x, (float)v0.y);
        __half2 h1 = __floats2half2_rn((float)v0.z, (float)v0.w);
        __half2 h2 = __floats2half2_rn((float)v1.x, (float)v1.y);
        __half2 h3 = __floats2half2_rn((float)v1.z, (float)v1.w);
        o[0] = *reinterpret_cast<uint32_t*>(&h0);
        o[1] = *reinterpret_cast<uint32_t*>(&h1);
        o[2] = *reinterpret_cast<uint32_t*>(&h2);
        o[3] = *reinterpret_cast<uint32_t*>(&h3);
    } else {
        const uint2* w = (const uint2*)wraw;
        uint2 r = w[i];
#pragma unroll
        for (int h = 0; h < 2; h++) {
            uint32_t v = h ? r.y : r.x;
            __half2 a = __floats2half2_rn((float)(int8_t)(v),
                                          (float)(int8_t)(v >> 8));
            __half2 b = __floats2half2_rn((float)(int8_t)(v >> 16),
                                          (float)(int8_t)(v >> 24));
            o[2 * h]     = *reinterpret_cast<uint32_t*>(&a);
            o[2 * h + 1] = *reinterpret_cast<uint32_t*>(&b);
        }
    }
    reinterpret_cast<uint4*>(g_w16)[i] = make_uint4(o[0], o[1], o[2], o[3]);
}

// ---------------------------------------------------------------------------
// GEMM: out[M,N] = X16[M,K] @ W16[N,K]^T
// CTA 128x128, 4 warps (2M x 2N), warp tile 64x64, BK=64, 3 stages,
// 2 CTAs/SM. Prefetch issues spread through the k-loop so LDGSTS issue
// never front-blocks HMMA issue.
// ---------------------------------------------------------------------------
__global__ void __launch_bounds__(128, 2) qlinear_gemm(
    const float* __restrict__ scale_w,
    const float* __restrict__ bias,
    float* __restrict__ out)
{
    extern __shared__ char smem[];
    const uint32_t sbase = smem_u32(smem);
    const int tid = threadIdx.x;
    const int wid = tid >> 5;
    const int lane = tid & 31;
    const int wm = wid & 1;              // 2 warps along M (64 rows each)
    const int wn = wid >> 1;             // 2 warps along N (64 cols each)

    // Grouped rasterization: 16 M-tiles per group (L2 reuse).
    const int tiles_n = N_TOTAL / BN;    // 128
    const int GH = 16;
    const int bid = blockIdx.x;
    const int group = bid / (GH * tiles_n);
    const int rem = bid % (GH * tiles_n);
    const int tile_m = group * GH + (rem % GH);
    const int tile_n = rem / GH;

    // ---- loop-invariant cp.async addressing ----
    const int c_row = tid >> 3;          // 0..15
    const int c_seg = tid & 7;           // 0..7
    const uint32_t dst0 = SWZ128((uint32_t)(c_row * 128 + c_seg * 16));
    const __half* srcA = g_x16 + (size_t)(tile_m * BM + c_row) * K_TOTAL + c_seg * 8;
    const __half* srcB = g_w16 + (size_t)(tile_n * BN + c_row) * K_TOTAL + c_seg * 8;

    // ---- loop-invariant ldmatrix offsets (k-step t: addr ^= t<<5) ----
    const int lrow = lane & 15;
    const int lcol = (lane >> 4) << 4;   // 0 or 16 bytes
    uint32_t offA[4], offB[4];
#pragma unroll
    for (int i = 0; i < 4; i++) {
        offA[i] = SWZ128((uint32_t)((wm * 64 + i * 16 + lrow) * 128 + lcol));
        offB[i] = SWZ128((uint32_t)((wn * 64 + i * 16 + lrow) * 128 + lcol))
                  + A_BYTES;
    }

    float acc[4][8][4];
#pragma unroll
    for (int i = 0; i < 4; i++)
#pragma unroll
        for (int j = 0; j < 8; j++)
#pragma unroll
            for (int v = 0; v < 4; v++) acc[i][j][v] = 0.f;

    // prologue: fill 2 stages (16 cp.async each, clumped — only happens twice)
#pragma unroll
    for (int p = 0; p < 2; p++) {
        uint32_t sb = sbase + (uint32_t)p * STAGE_BYTES;
#pragma unroll
        for (int it = 0; it < 8; it++) {
            cp_async16(sb + dst0 + it * 2048, srcA + (size_t)it * 16 * K_TOTAL);
            cp_async16(sb + A_BYTES + dst0 + it * 2048,
                       srcB + (size_t)it * 16 * K_TOTAL);
        }
        CP_COMMIT();
        srcA += BK;
        srcB += BK;
    }

    uint32_t st_cur = 0;                        // current stage offset
    uint32_t st_pre = 2 * STAGE_BYTES;          // prefetch stage offset

    for (int c = 0; c < NCHUNK; c++) {
        CP_WAIT(1);                  // chunk c resident
        __syncthreads();

        const uint32_t base = sbase + st_cur;
        const uint32_t pbase = sbase + st_pre;
        const bool do_pf = (c + 2 < NCHUNK);

        // hoist base into per-chunk absolute addresses (1 LOP3 per ldsm after)
        uint32_t adA[4], adB[4];
#pragma unroll
        for (int i = 0; i < 4; i++) { adA[i] = base + offA[i];
                                      adB[i] = base + offB[i]; }

#pragma unroll
        for (int t = 0; t < 4; t++) {    // four k16 steps per chunk
            // ---- 4 prefetch slivers: 2 A rows + 2 B rows per k-step ----
            if (do_pf) {
#pragma unroll
                for (int q = 0; q < 2; q++) {
                    int it = t * 2 + q;
                    cp_async16(pbase + dst0 + it * 2048,
                               srcA + (size_t)it * 16 * K_TOTAL);
                    cp_async16(pbase + A_BYTES + dst0 + it * 2048,
                               srcB + (size_t)it * 16 * K_TOTAL);
                }
            }

            const uint32_t tx = (uint32_t)(t << 5);
            uint32_t a[4][4];
            uint32_t b[8][2];
#pragma unroll
            for (int i = 0; i < 4; i++)
                ldsm_x4(a[i][0], a[i][1], a[i][2], a[i][3], adA[i] ^ tx);
#pragma unroll
            for (int jj = 0; jj < 4; jj++) {
                uint32_t r0, r1, r2, r3;
                ldsm_x4(r0, r1, r2, r3, adB[jj] ^ tx);
                b[2 * jj][0] = r0;     b[2 * jj][1] = r2;
                b[2 * jj + 1][0] = r1; b[2 * jj + 1][1] = r3;
            }
#pragma unroll
            for (int i = 0; i < 4; i++)
#pragma unroll
                for (int j = 0; j < 8; j++)
                    mma16816(acc[i][j], a[i], b[j]);
        }

        CP_COMMIT();
        srcA += BK;
        srcB += BK;
        st_pre += STAGE_BYTES; if (st_pre == STAGES * STAGE_BYTES) st_pre = 0;
        st_cur += STAGE_BYTES; if (st_cur == STAGES * STAGE_BYTES) st_cur = 0;
    }

    // ------------------------- Epilogue -----------------------------------
    // d frag: c0=(m=g, n=2u), c1=(g, 2u+1), c2=(g+8, 2u), c3=(g+8, 2u+1)
    const int g = lane >> 2;
    const int u = lane & 3;
#pragma unroll
    for (int i = 0; i < 4; i++) {
        int row0 = tile_m * BM + wm * 64 + i * 16 + g;
#pragma unroll
        for (int j = 0; j < 8; j++) {
            int col = tile_n * BN + wn * 64 + j * 8 + 2 * u;
            float2 sc = *(const float2*)(scale_w + col);
            float2 bi = *(const float2*)(bias + col);
            float2 y0 = make_float2(acc[i][j][0] * sc.x + bi.x,
                                    acc[i][j][1] * sc.y + bi.y);
            float2 y1 = make_float2(acc[i][j][2] * sc.x + bi.x,
                                    acc[i][j][3] * sc.y + bi.y);
            *(float2*)(out + (size_t)row0 * N_TOTAL + col) = y0;
            *(float2*)(out + (size_t)(row0 + 8) * N_TOTAL + col) = y1;
        }
    }
}

// ---------------------------------------------------------------------------
// kernel_launch
// ---------------------------------------------------------------------------
extern "C" void kernel_launch(void* const* d_in, const int* in_sizes, int n_in,
                              void* d_out, int out_size) {
    const float* x = (const float*)d_in[0];
    const void* wq = d_in[1];
    const float* scale = (const float*)d_in[2];
    const float* bias = (const float*)d_in[3];
    float* out = (float*)d_out;

    detect_w_kernel<<<1, 256>>>((const int4*)wq);
    cvt_x_kernel<<<(int)((size_t)M_TOTAL * K_TOTAL / 4 / 256), 256>>>((const float4*)x);
    cvt_w_kernel<<<(int)((size_t)N_TOTAL * K_TOTAL / 8 / 256), 256>>>(wq);

    cudaFuncSetAttribute(qlinear_gemm,
                         cudaFuncAttributeMaxDynamicSharedMemorySize, SMEM_GEMM);
    const int grid = (M_TOTAL / BM) * (N_TOTAL / BN);   // 8192
    qlinear_gemm<<<grid, 128, SMEM_GEMM>>>(scale, bias, out);
}

// round 9
// speedup vs baseline: 1.5021x; 1.5021x over previous
#include <cuda_runtime.h>
#include <cuda_fp16.h>
#include <cstdint>

// ---------------------------------------------------------------------------
// Problem constants
// ---------------------------------------------------------------------------
#define M_TOTAL 8192
#define N_TOTAL 16384
#define K_TOTAL 4096

#define BM 128
#define BN 128
#define BK 64                          // fp16 elems per K chunk (128 B rows)
#define NCHUNK (K_TOTAL / BK)          // 64
#define STAGES 3
#define A_BYTES 16384u                 // 128 rows * 128 B
#define STAGE_BYTES (2u * A_BYTES)     // A + B = 32768
#define SMEM_GEMM (STAGES * STAGE_BYTES)       // 98304 -> 2 CTAs/SM

// fp16 staging buffers (allocation-free scratch: __device__ globals)
__device__ __half g_x16[(size_t)M_TOTAL * K_TOTAL];   // 64 MB
__device__ __half g_w16[(size_t)N_TOTAL * K_TOTAL];   // 128 MB
__device__ int g_w_is_i32;             // weight dtype flag (detect kernel)

// ---------------------------------------------------------------------------
// Helpers
// ---------------------------------------------------------------------------
__device__ __forceinline__ uint32_t smem_u32(const void* p) {
    uint32_t r;
    asm("{ .reg .u64 t; cvta.to.shared.u64 t, %1; cvt.u32.u64 %0, t; }"
        : "=r"(r) : "l"(p));
    return r;
}

// Classic 128-byte-row swizzle: bits[6:4] ^= bits[9:7]. XOR-linear.
#define SWZ128(o) ((o) ^ (((o) >> 3) & 0x70))

__device__ __forceinline__ void cp_async16(uint32_t dst, const void* src) {
    asm volatile("cp.async.cg.shared.global [%0], [%1], 16;\n"
                 :: "r"(dst), "l"(src));
}
#define CP_COMMIT() asm volatile("cp.async.commit_group;\n" ::: "memory")
#define CP_WAIT(n)  asm volatile("cp.async.wait_group %0;\n" :: "n"(n) : "memory")

__device__ __forceinline__ void ldsm_x4(uint32_t& r0, uint32_t& r1,
                                        uint32_t& r2, uint32_t& r3,
                                        uint32_t addr) {
    asm volatile("ldmatrix.sync.aligned.m8n8.x4.shared.b16 {%0,%1,%2,%3}, [%4];"
                 : "=r"(r0), "=r"(r1), "=r"(r2), "=r"(r3) : "r"(addr));
}

__device__ __forceinline__ void mma16816(float* d, const uint32_t* a,
                                         const uint32_t* b) {
    asm volatile(
        "mma.sync.aligned.m16n8k16.row.col.f32.f16.f16.f32 "
        "{%0,%1,%2,%3}, {%4,%5,%6,%7}, {%8,%9}, {%0,%1,%2,%3};"
        : "+f"(d[0]), "+f"(d[1]), "+f"(d[2]), "+f"(d[3])
        : "r"(a[0]), "r"(a[1]), "r"(a[2]), "r"(a[3]), "r"(b[0]), "r"(b[1]));
}

// ---------------------------------------------------------------------------
// Weight dtype detection (int8 bytes read as int32 words land in [-127,127]
// with prob ~2^-24/word; all 16384 words in range <=> int32 buffer).
// ---------------------------------------------------------------------------
__global__ void __launch_bounds__(256) detect_w_kernel(const int4* __restrict__ w) {
    __shared__ int s_out_of_range;
    if (threadIdx.x == 0) s_out_of_range = 0;
    __syncthreads();
    int bad = 0;
#pragma unroll
    for (int it = 0; it < 16; it++) {
        int4 v = w[threadIdx.x * 16 + it];
        if (v.x < -127 || v.x > 127 || v.y < -127 || v.y > 127 ||
            v.z < -127 || v.z > 127 || v.w < -127 || v.w > 127) bad = 1;
    }
    if (bad) atomicOr(&s_out_of_range, 1);
    __syncthreads();
    if (threadIdx.x == 0) g_w_is_i32 = s_out_of_range ? 0 : 1;
}

// ---------------------------------------------------------------------------
// Conversion kernels
// ---------------------------------------------------------------------------
__global__ void __launch_bounds__(256) cvt_x_kernel(const float4* __restrict__ x) {
    size_t i = (size_t)blockIdx.x * blockDim.x + threadIdx.x;
    float4 v = x[i];
    __half2 a = __floats2half2_rn(v.x, v.y);
    __half2 b = __floats2half2_rn(v.z, v.w);
    reinterpret_cast<uint2*>(g_x16)[i] =
        make_uint2(*reinterpret_cast<uint32_t*>(&a),
                   *reinterpret_cast<uint32_t*>(&b));
}

__global__ void __launch_bounds__(256) cvt_w_kernel(const void* __restrict__ wraw) {
    size_t i = (size_t)blockIdx.x * blockDim.x + threadIdx.x;
    uint32_t o[4];
    if (g_w_is_i32) {
        const int4* w = (const int4*)wraw;
        int4 v0 = w[2 * i];
        int4 v1 = w[2 * i + 1];
        __half2 h0 = __floats2half2_rn((float)v0.x, (float)v0.y);
        __half2 h1 = __floats2half2_rn((float)v0.z, (float)v0.w);
        __half2 h2 = __floats2half2_rn((float)v1.x, (float)v1.y);
        __half2 h3 = __floats2half2_rn((float)v1.z, (float)v1.w);
        o[0] = *reinterpret_cast<uint32_t*>(&h0);
        o[1] = *reinterpret_cast<uint32_t*>(&h1);
        o[2] = *reinterpret_cast<uint32_t*>(&h2);
        o[3] = *reinterpret_cast<uint32_t*>(&h3);
    } else {
        const uint2* w = (const uint2*)wraw;
        uint2 r = w[i];
#pragma unroll
        for (int h = 0; h < 2; h++) {
            uint32_t v = h ? r.y : r.x;
            __half2 a = __floats2half2_rn((float)(int8_t)(v),
                                          (float)(int8_t)(v >> 8));
            __half2 b = __floats2half2_rn((float)(int8_t)(v >> 16),
                                          (float)(int8_t)(v >> 24));
            o[2 * h]     = *reinterpret_cast<uint32_t*>(&a);
            o[2 * h + 1] = *reinterpret_cast<uint32_t*>(&b);
        }
    }
    reinterpret_cast<uint4*>(g_w16)[i] = make_uint4(o[0], o[1], o[2], o[3]);
}

// ---------------------------------------------------------------------------
// GEMM: out[M,N] = X16[M,K] @ W16[N,K]^T
// CTA 128x128, 4 warps (2M x 2N), warp tile 64x64, BK=64, 3 stages,
// 2 CTAs/SM. R7 structure + rolling k-step fragment double-buffer:
// ldsm(t+1) issues before MMA(t) so its latency drains under the MMA block.
// ---------------------------------------------------------------------------
__global__ void __launch_bounds__(128, 2) qlinear_gemm(
    const float* __restrict__ scale_w,
    const float* __restrict__ bias,
    float* __restrict__ out)
{
    extern __shared__ char smem[];
    const uint32_t sbase = smem_u32(smem);
    const int tid = threadIdx.x;
    const int wid = tid >> 5;
    const int lane = tid & 31;
    const int wm = wid & 1;              // 2 warps along M (64 rows each)
    const int wn = wid >> 1;             // 2 warps along N (64 cols each)

    // Grouped rasterization: 16 M-tiles per group (L2 reuse).
    const int tiles_n = N_TOTAL / BN;    // 128
    const int GH = 16;
    const int bid = blockIdx.x;
    const int group = bid / (GH * tiles_n);
    const int rem = bid % (GH * tiles_n);
    const int tile_m = group * GH + (rem % GH);
    const int tile_n = rem / GH;

    // ---- loop-invariant cp.async addressing ----
    const int c_row = tid >> 3;          // 0..15
    const int c_seg = tid & 7;           // 0..7
    const uint32_t dst0 = SWZ128((uint32_t)(c_row * 128 + c_seg * 16));
    const __half* srcA = g_x16 + (size_t)(tile_m * BM + c_row) * K_TOTAL + c_seg * 8;
    const __half* srcB = g_w16 + (size_t)(tile_n * BN + c_row) * K_TOTAL + c_seg * 8;

    auto load_chunk = [&](uint32_t sb) {
#pragma unroll
        for (int it = 0; it < 8; it++)
            cp_async16(sb + dst0 + it * 2048,
                       srcA + (size_t)it * 16 * K_TOTAL);
#pragma unroll
        for (int it = 0; it < 8; it++)
            cp_async16(sb + A_BYTES + dst0 + it * 2048,
                       srcB + (size_t)it * 16 * K_TOTAL);
        srcA += BK;                      // advance to next K chunk
        srcB += BK;
    };

    // ---- loop-invariant ldmatrix offsets (k-step t: addr ^= t<<5) ----
    const int lrow = lane & 15;
    const int lcol = (lane >> 4) << 4;   // 0 or 16 bytes
    uint32_t offA[4], offB[4];
#pragma unroll
    for (int i = 0; i < 4; i++) {
        offA[i] = SWZ128((uint32_t)((wm * 64 + i * 16 + lrow) * 128 + lcol));
        offB[i] = SWZ128((uint32_t)((wn * 64 + i * 16 + lrow) * 128 + lcol))
                  + A_BYTES;
    }

    float acc[4][8][4];
#pragma unroll
    for (int i = 0; i < 4; i++)
#pragma unroll
        for (int j = 0; j < 8; j++)
#pragma unroll
            for (int v = 0; v < 4; v++) acc[i][j][v] = 0.f;

    // prologue: fill 2 stages
    load_chunk(sbase);               CP_COMMIT();
    load_chunk(sbase + STAGE_BYTES); CP_COMMIT();

    uint32_t st_cur = 0;                        // current stage offset
    uint32_t st_pre = 2 * STAGE_BYTES;          // prefetch stage offset

    uint32_t afr[2][4][4];               // rolling A fragments
    uint32_t bfr[2][8][2];               // rolling B fragments

    for (int c = 0; c < NCHUNK; c++) {
        CP_WAIT(1);                  // chunk c resident
        __syncthreads();

        // prefetch clump (R7-proven placement)
        if (c + 2 < NCHUNK) load_chunk(sbase + st_pre);
        CP_COMMIT();
        st_pre += STAGE_BYTES; if (st_pre == STAGES * STAGE_BYTES) st_pre = 0;

        const uint32_t base = sbase + st_cur;
        st_cur += STAGE_BYTES; if (st_cur == STAGES * STAGE_BYTES) st_cur = 0;

        uint32_t adA[4], adB[4];
#pragma unroll
        for (int i = 0; i < 4; i++) { adA[i] = base + offA[i];
                                      adB[i] = base + offB[i]; }

        // load k-step 0 fragments into buffer 0
#pragma unroll
        for (int i = 0; i < 4; i++)
            ldsm_x4(afr[0][i][0], afr[0][i][1], afr[0][i][2], afr[0][i][3],
                    adA[i]);
#pragma unroll
        for (int jj = 0; jj < 4; jj++) {
            uint32_t r0, r1, r2, r3;
            ldsm_x4(r0, r1, r2, r3, adB[jj]);
            bfr[0][2 * jj][0] = r0;     bfr[0][2 * jj][1] = r2;
            bfr[0][2 * jj + 1][0] = r1; bfr[0][2 * jj + 1][1] = r3;
        }

#pragma unroll
        for (int t = 0; t < 4; t++) {
            const int cur = t & 1;
            const int nxt = cur ^ 1;
            if (t < 3) {                 // issue ldsm(t+1) before MMA(t)
                const uint32_t tx = (uint32_t)((t + 1) << 5);
#pragma unroll
                for (int i = 0; i < 4; i++)
                    ldsm_x4(afr[nxt][i][0], afr[nxt][i][1],
                            afr[nxt][i][2], afr[nxt][i][3], adA[i] ^ tx);
#pragma unroll
                for (int jj = 0; jj < 4; jj++) {
                    uint32_t r0, r1, r2, r3;
                    ldsm_x4(r0, r1, r2, r3, adB[jj] ^ tx);
                    bfr[nxt][2 * jj][0] = r0;     bfr[nxt][2 * jj][1] = r2;
                    bfr[nxt][2 * jj + 1][0] = r1; bfr[nxt][2 * jj + 1][1] = r3;
                }
            }
#pragma unroll
            for (int i = 0; i < 4; i++)
#pragma unroll
                for (int j = 0; j < 8; j++)
                    mma16816(acc[i][j], afr[cur][i], bfr[cur][j]);
        }
    }

    // ------------------------- Epilogue -----------------------------------
    // d frag: c0=(m=g, n=2u), c1=(g, 2u+1), c2=(g+8, 2u), c3=(g+8, 2u+1)
    const int g = lane >> 2;
    const int u = lane & 3;
#pragma unroll
    for (int i = 0; i < 4; i++) {
        int row0 = tile_m * BM + wm * 64 + i * 16 + g;
#pragma unroll
        for (int j = 0; j < 8; j++) {
            int col = tile_n * BN + wn * 64 + j * 8 + 2 * u;
            float2 sc = *(const float2*)(scale_w + col);
            float2 bi = *(const float2*)(bias + col);
            float2 y0 = make_float2(acc[i][j][0] * sc.x + bi.x,
                                    acc[i][j][1] * sc.y + bi.y);
            float2 y1 = make_float2(acc[i][j][2] * sc.x + bi.x,
                                    acc[i][j][3] * sc.y + bi.y);
            *(float2*)(out + (size_t)row0 * N_TOTAL + col) = y0;
            *(float2*)(out + (size_t)(row0 + 8) * N_TOTAL + col) = y1;
        }
    }
}

// ---------------------------------------------------------------------------
// kernel_launch
// ---------------------------------------------------------------------------
extern "C" void kernel_launch(void* const* d_in, const int* in_sizes, int n_in,
                              void* d_out, int out_size) {
    const float* x = (const float*)d_in[0];
    const void* wq = d_in[1];
    const float* scale = (const float*)d_in[2];
    const float* bias = (const float*)d_in[3];
    float* out = (float*)d_out;

    detect_w_kernel<<<1, 256>>>((const int4*)wq);
    cvt_x_kernel<<<(int)((size_t)M_TOTAL * K_TOTAL / 4 / 256), 256>>>((const float4*)x);
    cvt_w_kernel<<<(int)((size_t)N_TOTAL * K_TOTAL / 8 / 256), 256>>>(wq);

    cudaFuncSetAttribute(qlinear_gemm,
                         cudaFuncAttributeMaxDynamicSharedMemorySize, SMEM_GEMM);
    const int grid = (M_TOTAL / BM) * (N_TOTAL / BN);   // 8192
    qlinear_gemm<<<grid, 128, SMEM_GEMM>>>(scale, bias, out);
}

// round 10
// speedup vs baseline: 1.5748x; 1.0484x over previous
#include <cuda_runtime.h>
#include <cuda_fp16.h>
#include <cstdint>

// ---------------------------------------------------------------------------
// Problem constants
// ---------------------------------------------------------------------------
#define M_TOTAL 8192
#define N_TOTAL 16384
#define K_TOTAL 4096

#define BM 128
#define BN 128
#define BK 64                          // fp16 elems per K chunk (128 B rows)
#define NCHUNK (K_TOTAL / BK)          // 64
#define STAGES 3
#define A_BYTES 16384u                 // 128 rows * 128 B
#define STAGE_BYTES (2u * A_BYTES)     // A + B = 32768
#define SMEM_GEMM (STAGES * STAGE_BYTES)       // 98304 -> 2 CTAs/SM

// fp16 staging buffers (allocation-free scratch). Padded by one K-row so the
// unconditional tail prefetch (up to 2 chunks past K) stays in-bounds.
__device__ __half g_x16[(size_t)M_TOTAL * K_TOTAL + K_TOTAL];   // 64 MB + pad
__device__ __half g_w16[(size_t)N_TOTAL * K_TOTAL + K_TOTAL];   // 128 MB + pad
__device__ int g_w_is_i32;             // weight dtype flag (detect kernel)

// ---------------------------------------------------------------------------
// Helpers
// ---------------------------------------------------------------------------
__device__ __forceinline__ uint32_t smem_u32(const void* p) {
    uint32_t r;
    asm("{ .reg .u64 t; cvta.to.shared.u64 t, %1; cvt.u32.u64 %0, t; }"
        : "=r"(r) : "l"(p));
    return r;
}

// Classic 128-byte-row swizzle: bits[6:4] ^= bits[9:7]. XOR-linear.
#define SWZ128(o) ((o) ^ (((o) >> 3) & 0x70))

__device__ __forceinline__ void cp_async16(uint32_t dst, const void* src) {
    asm volatile("cp.async.cg.shared.global [%0], [%1], 16;\n"
                 :: "r"(dst), "l"(src));
}
#define CP_COMMIT() asm volatile("cp.async.commit_group;\n" ::: "memory")
#define CP_WAIT(n)  asm volatile("cp.async.wait_group %0;\n" :: "n"(n) : "memory")

__device__ __forceinline__ void ldsm_x4(uint32_t& r0, uint32_t& r1,
                                        uint32_t& r2, uint32_t& r3,
                                        uint32_t addr) {
    asm volatile("ldmatrix.sync.aligned.m8n8.x4.shared.b16 {%0,%1,%2,%3}, [%4];"
                 : "=r"(r0), "=r"(r1), "=r"(r2), "=r"(r3) : "r"(addr));
}

__device__ __forceinline__ void mma16816(float* d, const uint32_t* a,
                                         const uint32_t* b) {
    asm volatile(
        "mma.sync.aligned.m16n8k16.row.col.f32.f16.f16.f32 "
        "{%0,%1,%2,%3}, {%4,%5,%6,%7}, {%8,%9}, {%0,%1,%2,%3};"
        : "+f"(d[0]), "+f"(d[1]), "+f"(d[2]), "+f"(d[3])
        : "r"(a[0]), "r"(a[1]), "r"(a[2]), "r"(a[3]), "r"(b[0]), "r"(b[1]));
}

// ---------------------------------------------------------------------------
// Weight dtype detection (int8 bytes read as int32 words land in [-127,127]
// with prob ~2^-24/word; all 16384 words in range <=> int32 buffer).
// ---------------------------------------------------------------------------
__global__ void __launch_bounds__(256) detect_w_kernel(const int4* __restrict__ w) {
    __shared__ int s_out_of_range;
    if (threadIdx.x == 0) s_out_of_range = 0;
    __syncthreads();
    int bad = 0;
#pragma unroll
    for (int it = 0; it < 16; it++) {
        int4 v = w[threadIdx.x * 16 + it];
        if (v.x < -127 || v.x > 127 || v.y < -127 || v.y > 127 ||
            v.z < -127 || v.z > 127 || v.w < -127 || v.w > 127) bad = 1;
    }
    if (bad) atomicOr(&s_out_of_range, 1);
    __syncthreads();
    if (threadIdx.x == 0) g_w_is_i32 = s_out_of_range ? 0 : 1;
}

// ---------------------------------------------------------------------------
// Conversion kernels
// ---------------------------------------------------------------------------
__global__ void __launch_bounds__(256) cvt_x_kernel(const float4* __restrict__ x) {
    size_t i = (size_t)blockIdx.x * blockDim.x + threadIdx.x;
    float4 v = x[i];
    __half2 a = __floats2half2_rn(v.x, v.y);
    __half2 b = __floats2half2_rn(v.z, v.w);
    reinterpret_cast<uint2*>(g_x16)[i] =
        make_uint2(*reinterpret_cast<uint32_t*>(&a),
                   *reinterpret_cast<uint32_t*>(&b));
}

__global__ void __launch_bounds__(256) cvt_w_kernel(const void* __restrict__ wraw) {
    size_t i = (size_t)blockIdx.x * blockDim.x + threadIdx.x;
    uint32_t o[4];
    if (g_w_is_i32) {
        const int4* w = (const int4*)wraw;
        int4 v0 = w[2 * i];
        int4 v1 = w[2 * i + 1];
        __half2 h0 = __floats2half2_rn((float)v0.x, (float)v0.y);
        __half2 h1 = __floats2half2_rn((float)v0.z, (float)v0.w);
        __half2 h2 = __floats2half2_rn((float)v1.x, (float)v1.y);
        __half2 h3 = __floats2half2_rn((float)v1.z, (float)v1.w);
        o[0] = *reinterpret_cast<uint32_t*>(&h0);
        o[1] = *reinterpret_cast<uint32_t*>(&h1);
        o[2] = *reinterpret_cast<uint32_t*>(&h2);
        o[3] = *reinterpret_cast<uint32_t*>(&h3);
    } else {
        const uint2* w = (const uint2*)wraw;
        uint2 r = w[i];
#pragma unroll
        for (int h = 0; h < 2; h++) {
            uint32_t v = h ? r.y : r.x;
            __half2 a = __floats2half2_rn((float)(int8_t)(v),
                                          (float)(int8_t)(v >> 8));
            __half2 b = __floats2half2_rn((float)(int8_t)(v >> 16),
                                          (float)(int8_t)(v >> 24));
            o[2 * h]     = *reinterpret_cast<uint32_t*>(&a);
            o[2 * h + 1] = *reinterpret_cast<uint32_t*>(&b);
        }
    }
    reinterpret_cast<uint4*>(g_w16)[i] = make_uint4(o[0], o[1], o[2], o[3]);
}

// ---------------------------------------------------------------------------
// GEMM: out[M,N] = X16[M,K] @ W16[N,K]^T
// CTA 128x128, 4 warps (2M x 2N), warp tile 64x64, BK=64, 3 stages,
// 2 CTAs/SM. R7 body, mainloop unrolled by STAGES=3 so every stage offset
// is a compile-time immediate (no stage-pointer ALU, no prefetch branch).
// ---------------------------------------------------------------------------
__global__ void __launch_bounds__(128, 2) qlinear_gemm(
    const float* __restrict__ scale_w,
    const float* __restrict__ bias,
    float* __restrict__ out)
{
    extern __shared__ char smem[];
    const uint32_t sbase = smem_u32(smem);
    const int tid = threadIdx.x;
    const int wid = tid >> 5;
    const int lane = tid & 31;
    const int wm = wid & 1;              // 2 warps along M (64 rows each)
    const int wn = wid >> 1;             // 2 warps along N (64 cols each)

    // Grouped rasterization: 16 M-tiles per group (L2 reuse).
    const int tiles_n = N_TOTAL / BN;    // 128
    const int GH = 16;
    const int bid = blockIdx.x;
    const int group = bid / (GH * tiles_n);
    const int rem = bid % (GH * tiles_n);
    const int tile_m = group * GH + (rem % GH);
    const int tile_n = rem / GH;

    // ---- loop-invariant cp.async addressing ----
    const int c_row = tid >> 3;          // 0..15
    const int c_seg = tid & 7;           // 0..7
    const uint32_t dstA = sbase + SWZ128((uint32_t)(c_row * 128 + c_seg * 16));
    const __half* srcA = g_x16 + (size_t)(tile_m * BM + c_row) * K_TOTAL + c_seg * 8;
    const __half* srcB = g_w16 + (size_t)(tile_n * BN + c_row) * K_TOTAL + c_seg * 8;

    // load one chunk into stage S (compile-time): all offsets immediates.
    auto load_chunk = [&](uint32_t stage_off) {
#pragma unroll
        for (int it = 0; it < 8; it++)
            cp_async16(dstA + stage_off + it * 2048,
                       srcA + (size_t)it * 16 * K_TOTAL);
#pragma unroll
        for (int it = 0; it < 8; it++)
            cp_async16(dstA + stage_off + A_BYTES + it * 2048,
                       srcB + (size_t)it * 16 * K_TOTAL);
        srcA += BK;                      // advance to next K chunk
        srcB += BK;
    };

    // ---- loop-invariant ldmatrix absolute addresses (stage 0) ----
    const int lrow = lane & 15;
    const int lcol = (lane >> 4) << 4;   // 0 or 16 bytes
    uint32_t absA[4], absB[4];
#pragma unroll
    for (int i = 0; i < 4; i++) {
        absA[i] = sbase + SWZ128((uint32_t)((wm * 64 + i * 16 + lrow) * 128 + lcol));
        absB[i] = sbase + SWZ128((uint32_t)((wn * 64 + i * 16 + lrow) * 128 + lcol))
                  + A_BYTES;
    }

    float acc[4][8][4];
#pragma unroll
    for (int i = 0; i < 4; i++)
#pragma unroll
        for (int j = 0; j < 8; j++)
#pragma unroll
            for (int v = 0; v < 4; v++) acc[i][j][v] = 0.f;

    // prologue: fill stages 0,1
    load_chunk(0);           CP_COMMIT();
    load_chunk(STAGE_BYTES); CP_COMMIT();

    // one chunk body: consume stage CUR, prefetch into stage PRE (immediates)
    auto chunk_body = [&](uint32_t cur_off, uint32_t pre_off) {
        CP_WAIT(1);
        __syncthreads();
        load_chunk(pre_off);             // unconditional (scratch is padded)
        CP_COMMIT();
#pragma unroll
        for (int t = 0; t < 4; t++) {
            const uint32_t tx = (uint32_t)(t << 5);
            uint32_t a[4][4];
            uint32_t b[8][2];
#pragma unroll
            for (int i = 0; i < 4; i++)
                ldsm_x4(a[i][0], a[i][1], a[i][2], a[i][3],
                        (absA[i] + cur_off) ^ tx);
#pragma unroll
            for (int jj = 0; jj < 4; jj++) {
                uint32_t r0, r1, r2, r3;
                ldsm_x4(r0, r1, r2, r3, (absB[jj] + cur_off) ^ tx);
                b[2 * jj][0] = r0;     b[2 * jj][1] = r2;
                b[2 * jj + 1][0] = r1; b[2 * jj + 1][1] = r3;
            }
#pragma unroll
            for (int i = 0; i < 4; i++)
#pragma unroll
                for (int j = 0; j < 8; j++)
                    mma16816(acc[i][j], a[i], b[j]);
        }
    };

    // 63 chunks in groups of 3 (stage offsets are literals), then 1 tail.
    for (int cc = 0; cc < NCHUNK - 1; cc += 3) {
        chunk_body(0u,               2u * STAGE_BYTES);
        chunk_body(STAGE_BYTES,      0u);
        chunk_body(2u * STAGE_BYTES, STAGE_BYTES);
    }
    chunk_body(0u, 2u * STAGE_BYTES);    // chunk 63 (63 % 3 == 0 -> stage 0)

    // ------------------------- Epilogue -----------------------------------
    // d frag: c0=(m=g, n=2u), c1=(g, 2u+1), c2=(g+8, 2u), c3=(g+8, 2u+1)
    const int g = lane >> 2;
    const int u = lane & 3;
#pragma unroll
    for (int i = 0; i < 4; i++) {
        int row0 = tile_m * BM + wm * 64 + i * 16 + g;
#pragma unroll
        for (int j = 0; j < 8; j++) {
            int col = tile_n * BN + wn * 64 + j * 8 + 2 * u;
            float2 sc = *(const float2*)(scale_w + col);
            float2 bi = *(const float2*)(bias + col);
            float2 y0 = make_float2(acc[i][j][0] * sc.x + bi.x,
                                    acc[i][j][1] * sc.y + bi.y);
            float2 y1 = make_float2(acc[i][j][2] * sc.x + bi.x,
                                    acc[i][j][3] * sc.y + bi.y);
            *(float2*)(out + (size_t)row0 * N_TOTAL + col) = y0;
            *(float2*)(out + (size_t)(row0 + 8) * N_TOTAL + col) = y1;
        }
    }
}

// ---------------------------------------------------------------------------
// kernel_launch
// ---------------------------------------------------------------------------
extern "C" void kernel_launch(void* const* d_in, const int* in_sizes, int n_in,
                              void* d_out, int out_size) {
    const float* x = (const float*)d_in[0];
    const void* wq = d_in[1];
    const float* scale = (const float*)d_in[2];
    const float* bias = (const float*)d_in[3];
    float* out = (float*)d_out;

    detect_w_kernel<<<1, 256>>>((const int4*)wq);
    cvt_x_kernel<<<(int)((size_t)M_TOTAL * K_TOTAL / 4 / 256), 256>>>((const float4*)x);
    cvt_w_kernel<<<(int)((size_t)N_TOTAL * K_TOTAL / 8 / 256), 256>>>(wq);

    cudaFuncSetAttribute(qlinear_gemm,
                         cudaFuncAttributeMaxDynamicSharedMemorySize, SMEM_GEMM);
    const int grid = (M_TOTAL / BM) * (N_TOTAL / BN);   // 8192
    qlinear_gemm<<<grid, 128, SMEM_GEMM>>>(scale, bias, out);
}

// round 11
// speedup vs baseline: 1.6296x; 1.0348x over previous
#include <cuda_runtime.h>
#include <cuda_fp16.h>
#include <cstdint>

// ---------------------------------------------------------------------------
// Problem constants
// ---------------------------------------------------------------------------
#define M_TOTAL 8192
#define N_TOTAL 16384
#define K_TOTAL 4096

#define BM 128
#define BN 128
#define BK 64                          // fp16 elems per K chunk (128 B rows)
#define NCHUNK (K_TOTAL / BK)          // 64
#define STAGES 3
#define A_BYTES 16384u                 // 128 rows * 128 B
#define STAGE_BYTES (2u * A_BYTES)     // A + B = 32768
#define SMEM_GEMM (STAGES * STAGE_BYTES)       // 98304 -> 2 CTAs/SM

// fp16 staging buffers (allocation-free scratch). Padded by one K-row so the
// unconditional tail prefetch (up to 2 chunks past K) stays in-bounds.
__device__ __half g_x16[(size_t)M_TOTAL * K_TOTAL + K_TOTAL];   // 64 MB + pad
__device__ __half g_w16[(size_t)N_TOTAL * K_TOTAL + K_TOTAL];   // 128 MB + pad
__device__ int g_w_is_i32;             // weight dtype flag (detect kernel)

// ---------------------------------------------------------------------------
// Helpers
// ---------------------------------------------------------------------------
__device__ __forceinline__ uint32_t smem_u32(const void* p) {
    uint32_t r;
    asm("{ .reg .u64 t; cvta.to.shared.u64 t, %1; cvt.u32.u64 %0, t; }"
        : "=r"(r) : "l"(p));
    return r;
}

// Classic 128-byte-row swizzle: bits[6:4] ^= bits[9:7]. XOR-linear.
#define SWZ128(o) ((o) ^ (((o) >> 3) & 0x70))

__device__ __forceinline__ void cp_async16(uint32_t dst, const void* src) {
    asm volatile("cp.async.cg.shared.global [%0], [%1], 16;\n"
                 :: "r"(dst), "l"(src));
}
#define CP_COMMIT() asm volatile("cp.async.commit_group;\n" ::: "memory")
#define CP_WAIT(n)  asm volatile("cp.async.wait_group %0;\n" :: "n"(n) : "memory")

__device__ __forceinline__ void ldsm_x4(uint32_t& r0, uint32_t& r1,
                                        uint32_t& r2, uint32_t& r3,
                                        uint32_t addr) {
    asm volatile("ldmatrix.sync.aligned.m8n8.x4.shared.b16 {%0,%1,%2,%3}, [%4];"
                 : "=r"(r0), "=r"(r1), "=r"(r2), "=r"(r3) : "r"(addr));
}

__device__ __forceinline__ void mma16816(float* d, const uint32_t* a,
                                         const uint32_t* b) {
    asm volatile(
        "mma.sync.aligned.m16n8k16.row.col.f32.f16.f16.f32 "
        "{%0,%1,%2,%3}, {%4,%5,%6,%7}, {%8,%9}, {%0,%1,%2,%3};"
        : "+f"(d[0]), "+f"(d[1]), "+f"(d[2]), "+f"(d[3])
        : "r"(a[0]), "r"(a[1]), "r"(a[2]), "r"(a[3]), "r"(b[0]), "r"(b[1]));
}

// ---------------------------------------------------------------------------
// Weight dtype detection (int8 bytes read as int32 words land in [-127,127]
// with prob ~2^-24/word; all 16384 words in range <=> int32 buffer).
// ---------------------------------------------------------------------------
__global__ void __launch_bounds__(256) detect_w_kernel(const int4* __restrict__ w) {
    __shared__ int s_out_of_range;
    if (threadIdx.x == 0) s_out_of_range = 0;
    __syncthreads();
    int bad = 0;
#pragma unroll
    for (int it = 0; it < 16; it++) {
        int4 v = w[threadIdx.x * 16 + it];
        if (v.x < -127 || v.x > 127 || v.y < -127 || v.y > 127 ||
            v.z < -127 || v.z > 127 || v.w < -127 || v.w > 127) bad = 1;
    }
    if (bad) atomicOr(&s_out_of_range, 1);
    __syncthreads();
    if (threadIdx.x == 0) g_w_is_i32 = s_out_of_range ? 0 : 1;
}

// ---------------------------------------------------------------------------
// Conversion kernels
// ---------------------------------------------------------------------------
__global__ void __launch_bounds__(256) cvt_x_kernel(const float4* __restrict__ x) {
    size_t i = (size_t)blockIdx.x * blockDim.x + threadIdx.x;
    float4 v = x[i];
    __half2 a = __floats2half2_rn(v.x, v.y);
    __half2 b = __floats2half2_rn(v.z, v.w);
    reinterpret_cast<uint2*>(g_x16)[i] =
        make_uint2(*reinterpret_cast<uint32_t*>(&a),
                   *reinterpret_cast<uint32_t*>(&b));
}

__global__ void __launch_bounds__(256) cvt_w_kernel(const void* __restrict__ wraw) {
    size_t i = (size_t)blockIdx.x * blockDim.x + threadIdx.x;
    uint32_t o[4];
    if (g_w_is_i32) {
        const int4* w = (const int4*)wraw;
        int4 v0 = w[2 * i];
        int4 v1 = w[2 * i + 1];
        __half2 h0 = __floats2half2_rn((float)v0.x, (float)v0.y);
        __half2 h1 = __floats2half2_rn((float)v0.z, (float)v0.w);
        __half2 h2 = __floats2half2_rn((float)v1.x, (float)v1.y);
        __half2 h3 = __floats2half2_rn((float)v1.z, (float)v1.w);
        o[0] = *reinterpret_cast<uint32_t*>(&h0);
        o[1] = *reinterpret_cast<uint32_t*>(&h1);
        o[2] = *reinterpret_cast<uint32_t*>(&h2);
        o[3] = *reinterpret_cast<uint32_t*>(&h3);
    } else {
        const uint2* w = (const uint2*)wraw;
        uint2 r = w[i];
#pragma unroll
        for (int h = 0; h < 2; h++) {
            uint32_t v = h ? r.y : r.x;
            __half2 a = __floats2half2_rn((float)(int8_t)(v),
                                          (float)(int8_t)(v >> 8));
            __half2 b = __floats2half2_rn((float)(int8_t)(v >> 16),
                                          (float)(int8_t)(v >> 24));
            o[2 * h]     = *reinterpret_cast<uint32_t*>(&a);
            o[2 * h + 1] = *reinterpret_cast<uint32_t*>(&b);
        }
    }
    reinterpret_cast<uint4*>(g_w16)[i] = make_uint4(o[0], o[1], o[2], o[3]);
}

// ---------------------------------------------------------------------------
// GEMM: out[M,N] = X16[M,K] @ W16[N,K]^T
// CTA 128x128, 4 warps (2M x 2N), warp tile 64x64, BK=64, 3 stages,
// 2 CTAs/SM. Stage offsets are compile-time immediates. The prefetch clump
// is issued AFTER k-step 0's MMA block so LDGSTS issue drains under tensor
// work instead of front-blocking it.
// ---------------------------------------------------------------------------
__global__ void __launch_bounds__(128, 2) qlinear_gemm(
    const float* __restrict__ scale_w,
    const float* __restrict__ bias,
    float* __restrict__ out)
{
    extern __shared__ char smem[];
    const uint32_t sbase = smem_u32(smem);
    const int tid = threadIdx.x;
    const int wid = tid >> 5;
    const int lane = tid & 31;
    const int wm = wid & 1;              // 2 warps along M (64 rows each)
    const int wn = wid >> 1;             // 2 warps along N (64 cols each)

    // Grouped rasterization: 16 M-tiles per group (L2 reuse).
    const int tiles_n = N_TOTAL / BN;    // 128
    const int GH = 16;
    const int bid = blockIdx.x;
    const int group = bid / (GH * tiles_n);
    const int rem = bid % (GH * tiles_n);
    const int tile_m = group * GH + (rem % GH);
    const int tile_n = rem / GH;

    // ---- loop-invariant cp.async addressing ----
    const int c_row = tid >> 3;          // 0..15
    const int c_seg = tid & 7;           // 0..7
    const uint32_t dstA = sbase + SWZ128((uint32_t)(c_row * 128 + c_seg * 16));
    const __half* srcA = g_x16 + (size_t)(tile_m * BM + c_row) * K_TOTAL + c_seg * 8;
    const __half* srcB = g_w16 + (size_t)(tile_n * BN + c_row) * K_TOTAL + c_seg * 8;

    // load one chunk into stage S (compile-time): all offsets immediates.
    auto load_chunk = [&](uint32_t stage_off) {
#pragma unroll
        for (int it = 0; it < 8; it++)
            cp_async16(dstA + stage_off + it * 2048,
                       srcA + (size_t)it * 16 * K_TOTAL);
#pragma unroll
        for (int it = 0; it < 8; it++)
            cp_async16(dstA + stage_off + A_BYTES + it * 2048,
                       srcB + (size_t)it * 16 * K_TOTAL);
        srcA += BK;                      // advance to next K chunk
        srcB += BK;
    };

    // ---- loop-invariant ldmatrix absolute addresses (stage 0) ----
    const int lrow = lane & 15;
    const int lcol = (lane >> 4) << 4;   // 0 or 16 bytes
    uint32_t absA[4], absB[4];
#pragma unroll
    for (int i = 0; i < 4; i++) {
        absA[i] = sbase + SWZ128((uint32_t)((wm * 64 + i * 16 + lrow) * 128 + lcol));
        absB[i] = sbase + SWZ128((uint32_t)((wn * 64 + i * 16 + lrow) * 128 + lcol))
                  + A_BYTES;
    }

    float acc[4][8][4];
#pragma unroll
    for (int i = 0; i < 4; i++)
#pragma unroll
        for (int j = 0; j < 8; j++)
#pragma unroll
            for (int v = 0; v < 4; v++) acc[i][j][v] = 0.f;

    // prologue: fill stages 0,1
    load_chunk(0);           CP_COMMIT();
    load_chunk(STAGE_BYTES); CP_COMMIT();

    // one k16 step: ldsm + 32 MMA (homogeneous blocks)
    auto kstep = [&](uint32_t cur_off, int t) {
        const uint32_t tx = (uint32_t)(t << 5);
        uint32_t a[4][4];
        uint32_t b[8][2];
#pragma unroll
        for (int i = 0; i < 4; i++)
            ldsm_x4(a[i][0], a[i][1], a[i][2], a[i][3],
                    (absA[i] + cur_off) ^ tx);
#pragma unroll
        for (int jj = 0; jj < 4; jj++) {
            uint32_t r0, r1, r2, r3;
            ldsm_x4(r0, r1, r2, r3, (absB[jj] + cur_off) ^ tx);
            b[2 * jj][0] = r0;     b[2 * jj][1] = r2;
            b[2 * jj + 1][0] = r1; b[2 * jj + 1][1] = r3;
        }
#pragma unroll
        for (int i = 0; i < 4; i++)
#pragma unroll
            for (int j = 0; j < 8; j++)
                mma16816(acc[i][j], a[i], b[j]);
    };

    // chunk body: k0 first (tensor starts immediately), then prefetch clump,
    // then k1..k3. Prefetch targets stage (c+2)%3 != cur -> no hazard.
    auto chunk_body = [&](uint32_t cur_off, uint32_t pre_off) {
        CP_WAIT(1);
        __syncthreads();
        kstep(cur_off, 0);
        load_chunk(pre_off);             // unconditional (scratch is padded)
        CP_COMMIT();
        kstep(cur_off, 1);
        kstep(cur_off, 2);
        kstep(cur_off, 3);
    };

    // 63 chunks in groups of 3 (stage offsets are literals), then 1 tail.
    for (int cc = 0; cc < NCHUNK - 1; cc += 3) {
        chunk_body(0u,               2u * STAGE_BYTES);
        chunk_body(STAGE_BYTES,      0u);
        chunk_body(2u * STAGE_BYTES, STAGE_BYTES);
    }
    chunk_body(0u, 2u * STAGE_BYTES);    // chunk 63 (63 % 3 == 0 -> stage 0)

    // ------------------------- Epilogue -----------------------------------
    // d frag: c0=(m=g, n=2u), c1=(g, 2u+1), c2=(g+8, 2u), c3=(g+8, 2u+1)
    const int g = lane >> 2;
    const int u = lane & 3;
#pragma unroll
    for (int i = 0; i < 4; i++) {
        int row0 = tile_m * BM + wm * 64 + i * 16 + g;
#pragma unroll
        for (int j = 0; j < 8; j++) {
            int col = tile_n * BN + wn * 64 + j * 8 + 2 * u;
            float2 sc = *(const float2*)(scale_w + col);
            float2 bi = *(const float2*)(bias + col);
            float2 y0 = make_float2(acc[i][j][0] * sc.x + bi.x,
                                    acc[i][j][1] * sc.y + bi.y);
            float2 y1 = make_float2(acc[i][j][2] * sc.x + bi.x,
                                    acc[i][j][3] * sc.y + bi.y);
            *(float2*)(out + (size_t)row0 * N_TOTAL + col) = y0;
            *(float2*)(out + (size_t)(row0 + 8) * N_TOTAL + col) = y1;
        }
    }
}

// ---------------------------------------------------------------------------
// kernel_launch
// ---------------------------------------------------------------------------
extern "C" void kernel_launch(void* const* d_in, const int* in_sizes, int n_in,
                              void* d_out, int out_size) {
    const float* x = (const float*)d_in[0];
    const void* wq = d_in[1];
    const float* scale = (const float*)d_in[2];
    const float* bias = (const float*)d_in[3];
    float* out = (float*)d_out;

    detect_w_kernel<<<1, 256>>>((const int4*)wq);
    cvt_x_kernel<<<(int)((size_t)M_TOTAL * K_TOTAL / 4 / 256), 256>>>((const float4*)x);
    cvt_w_kernel<<<(int)((size_t)N_TOTAL * K_TOTAL / 8 / 256), 256>>>(wq);

    cudaFuncSetAttribute(qlinear_gemm,
                         cudaFuncAttributeMaxDynamicSharedMemorySize, SMEM_GEMM);
    const int grid = (M_TOTAL / BM) * (N_TOTAL / BN);   // 8192
    qlinear_gemm<<<grid, 128, SMEM_GEMM>>>(scale, bias, out);
}

// round 12
// speedup vs baseline: 1.6597x; 1.0185x over previous
#include <cuda_runtime.h>
#include <cuda_fp16.h>
#include <cstdint>

// ---------------------------------------------------------------------------
// Problem constants
// ---------------------------------------------------------------------------
#define M_TOTAL 8192
#define N_TOTAL 16384
#define K_TOTAL 4096

#define BM 128
#define BN 128
#define BK 64                          // fp16 elems per K chunk (128 B rows)
#define NCHUNK (K_TOTAL / BK)          // 64
#define STAGES 3
#define A_BYTES 16384u                 // 128 rows * 128 B
#define STAGE_BYTES (2u * A_BYTES)     // A + B = 32768
#define SMEM_GEMM (STAGES * STAGE_BYTES)       // 98304 -> 2 CTAs/SM

// fp16 staging buffers (allocation-free scratch). Padded by one K-row so the
// unconditional tail prefetch (up to 2 chunks past K) stays in-bounds.
__device__ __half g_x16[(size_t)M_TOTAL * K_TOTAL + K_TOTAL];   // 64 MB + pad
__device__ __half g_w16[(size_t)N_TOTAL * K_TOTAL + K_TOTAL];   // 128 MB + pad
__device__ int g_w_is_i32;             // weight dtype flag (detect kernel)

// ---------------------------------------------------------------------------
// Helpers
// ---------------------------------------------------------------------------
__device__ __forceinline__ uint32_t smem_u32(const void* p) {
    uint32_t r;
    asm("{ .reg .u64 t; cvta.to.shared.u64 t, %1; cvt.u32.u64 %0, t; }"
        : "=r"(r) : "l"(p));
    return r;
}

// Classic 128-byte-row swizzle: bits[6:4] ^= bits[9:7]. XOR-linear.
#define SWZ128(o) ((o) ^ (((o) >> 3) & 0x70))

__device__ __forceinline__ void cp_async16(uint32_t dst, const void* src) {
    asm volatile("cp.async.cg.shared.global [%0], [%1], 16;\n"
                 :: "r"(dst), "l"(src));
}
#define CP_COMMIT() asm volatile("cp.async.commit_group;\n" ::: "memory")
#define CP_WAIT(n)  asm volatile("cp.async.wait_group %0;\n" :: "n"(n) : "memory")

__device__ __forceinline__ void ldsm_x4(uint32_t& r0, uint32_t& r1,
                                        uint32_t& r2, uint32_t& r3,
                                        uint32_t addr) {
    asm volatile("ldmatrix.sync.aligned.m8n8.x4.shared.b16 {%0,%1,%2,%3}, [%4];"
                 : "=r"(r0), "=r"(r1), "=r"(r2), "=r"(r3) : "r"(addr));
}

__device__ __forceinline__ void mma16816(float* d, const uint32_t* a,
                                         const uint32_t* b) {
    asm volatile(
        "mma.sync.aligned.m16n8k16.row.col.f32.f16.f16.f32 "
        "{%0,%1,%2,%3}, {%4,%5,%6,%7}, {%8,%9}, {%0,%1,%2,%3};"
        : "+f"(d[0]), "+f"(d[1]), "+f"(d[2]), "+f"(d[3])
        : "r"(a[0]), "r"(a[1]), "r"(a[2]), "r"(a[3]), "r"(b[0]), "r"(b[1]));
}

// ---------------------------------------------------------------------------
// Weight dtype detection (int8 bytes read as int32 words land in [-127,127]
// with prob ~2^-24/word; all 16384 words in range <=> int32 buffer).
// ---------------------------------------------------------------------------
__global__ void __launch_bounds__(256) detect_w_kernel(const int4* __restrict__ w) {
    __shared__ int s_out_of_range;
    if (threadIdx.x == 0) s_out_of_range = 0;
    __syncthreads();
    int bad = 0;
#pragma unroll
    for (int it = 0; it < 16; it++) {
        int4 v = w[threadIdx.x * 16 + it];
        if (v.x < -127 || v.x > 127 || v.y < -127 || v.y > 127 ||
            v.z < -127 || v.z > 127 || v.w < -127 || v.w > 127) bad = 1;
    }
    if (bad) atomicOr(&s_out_of_range, 1);
    __syncthreads();
    if (threadIdx.x == 0) g_w_is_i32 = s_out_of_range ? 0 : 1;
}

// ---------------------------------------------------------------------------
// Conversion kernels
// ---------------------------------------------------------------------------
__global__ void __launch_bounds__(256) cvt_x_kernel(const float4* __restrict__ x) {
    size_t i = (size_t)blockIdx.x * blockDim.x + threadIdx.x;
    float4 v = x[i];
    __half2 a = __floats2half2_rn(v.x, v.y);
    __half2 b = __floats2half2_rn(v.z, v.w);
    reinterpret_cast<uint2*>(g_x16)[i] =
        make_uint2(*reinterpret_cast<uint32_t*>(&a),
                   *reinterpret_cast<uint32_t*>(&b));
}

__global__ void __launch_bounds__(256) cvt_w_kernel(const void* __restrict__ wraw) {
    size_t i = (size_t)blockIdx.x * blockDim.x + threadIdx.x;
    uint32_t o[4];
    if (g_w_is_i32) {
        const int4* w = (const int4*)wraw;
        int4 v0 = w[2 * i];
        int4 v1 = w[2 * i + 1];
        __half2 h0 = __floats2half2_rn((float)v0.x, (float)v0.y);
        __half2 h1 = __floats2half2_rn((float)v0.z, (float)v0.w);
        __half2 h2 = __floats2half2_rn((float)v1.x, (float)v1.y);
        __half2 h3 = __floats2half2_rn((float)v1.z, (float)v1.w);
        o[0] = *reinterpret_cast<uint32_t*>(&h0);
        o[1] = *reinterpret_cast<uint32_t*>(&h1);
        o[2] = *reinterpret_cast<uint32_t*>(&h2);
        o[3] = *reinterpret_cast<uint32_t*>(&h3);
    } else {
        const uint2* w = (const uint2*)wraw;
        uint2 r = w[i];
#pragma unroll
        for (int h = 0; h < 2; h++) {
            uint32_t v = h ? r.y : r.x;
            __half2 a = __floats2half2_rn((float)(int8_t)(v),
                                          (float)(int8_t)(v >> 8));
            __half2 b = __floats2half2_rn((float)(int8_t)(v >> 16),
                                          (float)(int8_t)(v >> 24));
            o[2 * h]     = *reinterpret_cast<uint32_t*>(&a);
            o[2 * h + 1] = *reinterpret_cast<uint32_t*>(&b);
        }
    }
    reinterpret_cast<uint4*>(g_w16)[i] = make_uint4(o[0], o[1], o[2], o[3]);
}

// ---------------------------------------------------------------------------
// GEMM: out[M,N] = X16[M,K] @ W16[N,K]^T
// CTA 128x128, 4 warps (2M x 2N), warp tile 64x64, BK=64, 3 stages,
// 2 CTAs/SM. Stage offsets are compile-time immediates. Prefetch is split
// into two homogeneous 8-clumps: A-half after k0's MMAs, B-half after k1's
// MMAs (single commit), so LDGSTS issue always drains under tensor work.
// ---------------------------------------------------------------------------
__global__ void __launch_bounds__(128, 2) qlinear_gemm(
    const float* __restrict__ scale_w,
    const float* __restrict__ bias,
    float* __restrict__ out)
{
    extern __shared__ char smem[];
    const uint32_t sbase = smem_u32(smem);
    const int tid = threadIdx.x;
    const int wid = tid >> 5;
    const int lane = tid & 31;
    const int wm = wid & 1;              // 2 warps along M (64 rows each)
    const int wn = wid >> 1;             // 2 warps along N (64 cols each)

    // Grouped rasterization: 16 M-tiles per group (L2 reuse).
    const int tiles_n = N_TOTAL / BN;    // 128
    const int GH = 16;
    const int bid = blockIdx.x;
    const int group = bid / (GH * tiles_n);
    const int rem = bid % (GH * tiles_n);
    const int tile_m = group * GH + (rem % GH);
    const int tile_n = rem / GH;

    // ---- loop-invariant cp.async addressing ----
    const int c_row = tid >> 3;          // 0..15
    const int c_seg = tid & 7;           // 0..7
    const uint32_t dstA = sbase + SWZ128((uint32_t)(c_row * 128 + c_seg * 16));
    const __half* srcA = g_x16 + (size_t)(tile_m * BM + c_row) * K_TOTAL + c_seg * 8;
    const __half* srcB = g_w16 + (size_t)(tile_n * BN + c_row) * K_TOTAL + c_seg * 8;

    // half-chunk loaders (stage offset is a compile-time immediate)
    auto load_A = [&](uint32_t stage_off) {
#pragma unroll
        for (int it = 0; it < 8; it++)
            cp_async16(dstA + stage_off + it * 2048,
                       srcA + (size_t)it * 16 * K_TOTAL);
        srcA += BK;
    };
    auto load_B = [&](uint32_t stage_off) {
#pragma unroll
        for (int it = 0; it < 8; it++)
            cp_async16(dstA + stage_off + A_BYTES + it * 2048,
                       srcB + (size_t)it * 16 * K_TOTAL);
        srcB += BK;
    };

    // ---- loop-invariant ldmatrix absolute addresses (stage 0) ----
    const int lrow = lane & 15;
    const int lcol = (lane >> 4) << 4;   // 0 or 16 bytes
    uint32_t absA[4], absB[4];
#pragma unroll
    for (int i = 0; i < 4; i++) {
        absA[i] = sbase + SWZ128((uint32_t)((wm * 64 + i * 16 + lrow) * 128 + lcol));
        absB[i] = sbase + SWZ128((uint32_t)((wn * 64 + i * 16 + lrow) * 128 + lcol))
                  + A_BYTES;
    }

    float acc[4][8][4];
#pragma unroll
    for (int i = 0; i < 4; i++)
#pragma unroll
        for (int j = 0; j < 8; j++)
#pragma unroll
            for (int v = 0; v < 4; v++) acc[i][j][v] = 0.f;

    // prologue: fill stages 0,1
    load_A(0);           load_B(0);           CP_COMMIT();
    load_A(STAGE_BYTES); load_B(STAGE_BYTES); CP_COMMIT();

    // one k16 step: ldsm + 32 MMA (homogeneous blocks)
    auto kstep = [&](uint32_t cur_off, int t) {
        const uint32_t tx = (uint32_t)(t << 5);
        uint32_t a[4][4];
        uint32_t b[8][2];
#pragma unroll
        for (int i = 0; i < 4; i++)
            ldsm_x4(a[i][0], a[i][1], a[i][2], a[i][3],
                    (absA[i] + cur_off) ^ tx);
#pragma unroll
        for (int jj = 0; jj < 4; jj++) {
            uint32_t r0, r1, r2, r3;
            ldsm_x4(r0, r1, r2, r3, (absB[jj] + cur_off) ^ tx);
            b[2 * jj][0] = r0;     b[2 * jj][1] = r2;
            b[2 * jj + 1][0] = r1; b[2 * jj + 1][1] = r3;
        }
#pragma unroll
        for (int i = 0; i < 4; i++)
#pragma unroll
            for (int j = 0; j < 8; j++)
                mma16816(acc[i][j], a[i], b[j]);
    };

    // chunk body: k0 -> A-prefetch clump -> k1 -> B-prefetch clump+commit ->
    // k2 -> k3. Prefetch targets stage (c+2)%3 != cur -> no hazard.
    auto chunk_body = [&](uint32_t cur_off, uint32_t pre_off) {
        CP_WAIT(1);
        __syncthreads();
        kstep(cur_off, 0);
        load_A(pre_off);                 // unconditional (scratch is padded)
        kstep(cur_off, 1);
        load_B(pre_off);
        CP_COMMIT();
        kstep(cur_off, 2);
        kstep(cur_off, 3);
    };

    // 63 chunks in groups of 3 (stage offsets are literals), then 1 tail.
    for (int cc = 0; cc < NCHUNK - 1; cc += 3) {
        chunk_body(0u,               2u * STAGE_BYTES);
        chunk_body(STAGE_BYTES,      0u);
        chunk_body(2u * STAGE_BYTES, STAGE_BYTES);
    }
    chunk_body(0u, 2u * STAGE_BYTES);    // chunk 63 (63 % 3 == 0 -> stage 0)

    // ------------------------- Epilogue -----------------------------------
    // d frag: c0=(m=g, n=2u), c1=(g, 2u+1), c2=(g+8, 2u), c3=(g+8, 2u+1)
    const int g = lane >> 2;
    const int u = lane & 3;
#pragma unroll
    for (int i = 0; i < 4; i++) {
        int row0 = tile_m * BM + wm * 64 + i * 16 + g;
#pragma unroll
        for (int j = 0; j < 8; j++) {
            int col = tile_n * BN + wn * 64 + j * 8 + 2 * u;
            float2 sc = *(const float2*)(scale_w + col);
            float2 bi = *(const float2*)(bias + col);
            float2 y0 = make_float2(acc[i][j][0] * sc.x + bi.x,
                                    acc[i][j][1] * sc.y + bi.y);
            float2 y1 = make_float2(acc[i][j][2] * sc.x + bi.x,
                                    acc[i][j][3] * sc.y + bi.y);
            *(float2*)(out + (size_t)row0 * N_TOTAL + col) = y0;
            *(float2*)(out + (size_t)(row0 + 8) * N_TOTAL + col) = y1;
        }
    }
}

// ---------------------------------------------------------------------------
// kernel_launch
// ---------------------------------------------------------------------------
extern "C" void kernel_launch(void* const* d_in, const int* in_sizes, int n_in,
                              void* d_out, int out_size) {
    const float* x = (const float*)d_in[0];
    const void* wq = d_in[1];
    const float* scale = (const float*)d_in[2];
    const float* bias = (const float*)d_in[3];
    float* out = (float*)d_out;

    detect_w_kernel<<<1, 256>>>((const int4*)wq);
    cvt_x_kernel<<<(int)((size_t)M_TOTAL * K_TOTAL / 4 / 256), 256>>>((const float4*)x);
    cvt_w_kernel<<<(int)((size_t)N_TOTAL * K_TOTAL / 8 / 256), 256>>>(wq);

    cudaFuncSetAttribute(qlinear_gemm,
                         cudaFuncAttributeMaxDynamicSharedMemorySize, SMEM_GEMM);
    const int grid = (M_TOTAL / BM) * (N_TOTAL / BN);   // 8192
    qlinear_gemm<<<grid, 128, SMEM_GEMM>>>(scale, bias, out);
}

// round 13
// speedup vs baseline: 1.6659x; 1.0037x over previous
#include <cuda_runtime.h>
#include <cuda_fp16.h>
#include <cstdint>

// ---------------------------------------------------------------------------
// Problem constants
// ---------------------------------------------------------------------------
#define M_TOTAL 8192
#define N_TOTAL 16384
#define K_TOTAL 4096

#define BM 128
#define BN 128
#define BK 64                          // fp16 elems per K chunk (128 B rows)
#define NCHUNK (K_TOTAL / BK)          // 64
#define STAGES 3
#define A_BYTES 16384u                 // 128 rows * 128 B
#define STAGE_BYTES (2u * A_BYTES)     // A + B = 32768
#define SMEM_GEMM (STAGES * STAGE_BYTES)       // 98304 -> 2 CTAs/SM

// fp16 staging buffers (allocation-free scratch). Padded by one K-row so the
// unconditional tail prefetch (up to 2 chunks past K) stays in-bounds.
__device__ __half g_x16[(size_t)M_TOTAL * K_TOTAL + K_TOTAL];   // 64 MB + pad
__device__ __half g_w16[(size_t)N_TOTAL * K_TOTAL + K_TOTAL];   // 128 MB + pad
__device__ int g_w_is_i32;             // weight dtype flag (detect kernel)

// ---------------------------------------------------------------------------
// Helpers
// ---------------------------------------------------------------------------
__device__ __forceinline__ uint32_t smem_u32(const void* p) {
    uint32_t r;
    asm("{ .reg .u64 t; cvta.to.shared.u64 t, %1; cvt.u32.u64 %0, t; }"
        : "=r"(r) : "l"(p));
    return r;
}

// Classic 128-byte-row swizzle: bits[6:4] ^= bits[9:7]. XOR-linear.
#define SWZ128(o) ((o) ^ (((o) >> 3) & 0x70))

__device__ __forceinline__ void cp_async16(uint32_t dst, const void* src) {
    asm volatile("cp.async.cg.shared.global [%0], [%1], 16;\n"
                 :: "r"(dst), "l"(src));
}
#define CP_COMMIT() asm volatile("cp.async.commit_group;\n" ::: "memory")
#define CP_WAIT(n)  asm volatile("cp.async.wait_group %0;\n" :: "n"(n) : "memory")

__device__ __forceinline__ void ldsm_x4(uint32_t& r0, uint32_t& r1,
                                        uint32_t& r2, uint32_t& r3,
                                        uint32_t addr) {
    asm volatile("ldmatrix.sync.aligned.m8n8.x4.shared.b16 {%0,%1,%2,%3}, [%4];"
                 : "=r"(r0), "=r"(r1), "=r"(r2), "=r"(r3) : "r"(addr));
}

__device__ __forceinline__ void mma16816(float* d, const uint32_t* a,
                                         const uint32_t* b) {
    asm volatile(
        "mma.sync.aligned.m16n8k16.row.col.f32.f16.f16.f32 "
        "{%0,%1,%2,%3}, {%4,%5,%6,%7}, {%8,%9}, {%0,%1,%2,%3};"
        : "+f"(d[0]), "+f"(d[1]), "+f"(d[2]), "+f"(d[3])
        : "r"(a[0]), "r"(a[1]), "r"(a[2]), "r"(a[3]), "r"(b[0]), "r"(b[1]));
}

// Streaming (no-reuse) 16B load/store for the convert pass.
__device__ __forceinline__ uint4 ldg_cs16(const void* p) {
    uint4 v;
    asm volatile("ld.global.cs.v4.u32 {%0,%1,%2,%3}, [%4];"
                 : "=r"(v.x), "=r"(v.y), "=r"(v.z), "=r"(v.w) : "l"(p));
    return v;
}
__device__ __forceinline__ void stg_cs16(void* p, uint4 v) {
    asm volatile("st.global.cs.v4.u32 [%0], {%1,%2,%3,%4};"
                 :: "l"(p), "r"(v.x), "r"(v.y), "r"(v.z), "r"(v.w));
}

// ---------------------------------------------------------------------------
// Weight dtype detection (int8 bytes read as int32 words land in [-127,127]
// with prob ~2^-24/word; all 16384 words in range <=> int32 buffer).
// ---------------------------------------------------------------------------
__global__ void __launch_bounds__(256) detect_w_kernel(const int4* __restrict__ w) {
    __shared__ int s_out_of_range;
    if (threadIdx.x == 0) s_out_of_range = 0;
    __syncthreads();
    int bad = 0;
#pragma unroll
    for (int it = 0; it < 16; it++) {
        int4 v = w[threadIdx.x * 16 + it];
        if (v.x < -127 || v.x > 127 || v.y < -127 || v.y > 127 ||
            v.z < -127 || v.z > 127 || v.w < -127 || v.w > 127) bad = 1;
    }
    if (bad) atomicOr(&s_out_of_range, 1);
    __syncthreads();
    if (threadIdx.x == 0) g_w_is_i32 = s_out_of_range ? 0 : 1;
}

// ---------------------------------------------------------------------------
// Fused conversion kernel: blocks [0, XB) convert x (fp32->fp16, 4/thread);
// blocks [XB, XB+WB) convert weights (int->fp16 exact, 8/thread).
// All traffic uses .cs streaming hints (zero reuse; keep L2 clean).
// ---------------------------------------------------------------------------
#define XB ((int)((size_t)M_TOTAL * K_TOTAL / 4 / 256))        // 8192
#define WB ((int)((size_t)N_TOTAL * K_TOTAL / 8 / 256))        // 32768

__global__ void __launch_bounds__(256) cvt_all_kernel(
    const float4* __restrict__ x, const void* __restrict__ wraw) {
    int b = blockIdx.x;
    if (b < XB) {
        size_t i = (size_t)b * 256 + threadIdx.x;
        uint4 raw = ldg_cs16(x + i);
        float4 v = *reinterpret_cast<float4*>(&raw);
        __half2 a = __floats2half2_rn(v.x, v.y);
        __half2 c = __floats2half2_rn(v.z, v.w);
        // pack 8B; pair threads via 16B granularity is overkill — use 8B st.cs
        uint2 o = make_uint2(*reinterpret_cast<uint32_t*>(&a),
                             *reinterpret_cast<uint32_t*>(&c));
        asm volatile("st.global.cs.v2.u32 [%0], {%1,%2};"
                     :: "l"(reinterpret_cast<uint2*>(g_x16) + i),
                        "r"(o.x), "r"(o.y));
    } else {
        size_t i = (size_t)(b - XB) * 256 + threadIdx.x;
        uint32_t o[4];
        if (g_w_is_i32) {
            const int4* w = (const int4*)wraw;
            uint4 r0 = ldg_cs16(w + 2 * i);
            uint4 r1 = ldg_cs16(w + 2 * i + 1);
            int4 v0 = *reinterpret_cast<int4*>(&r0);
            int4 v1 = *reinterpret_cast<int4*>(&r1);
            __half2 h0 = __floats2half2_rn((float)v0.x, (float)v0.y);
            __half2 h1 = __floats2half2_rn((float)v0.z, (float)v0.w);
            __half2 h2 = __floats2half2_rn((float)v1.x, (float)v1.y);
            __half2 h3 = __floats2half2_rn((float)v1.z, (float)v1.w);
            o[0] = *reinterpret_cast<uint32_t*>(&h0);
            o[1] = *reinterpret_cast<uint32_t*>(&h1);
            o[2] = *reinterpret_cast<uint32_t*>(&h2);
            o[3] = *reinterpret_cast<uint32_t*>(&h3);
        } else {
            const uint2* w = (const uint2*)wraw;
            uint2 r = w[i];
#pragma unroll
            for (int h = 0; h < 2; h++) {
                uint32_t v = h ? r.y : r.x;
                __half2 a = __floats2half2_rn((float)(int8_t)(v),
                                              (float)(int8_t)(v >> 8));
                __half2 c = __floats2half2_rn((float)(int8_t)(v >> 16),
                                              (float)(int8_t)(v >> 24));
                o[2 * h]     = *reinterpret_cast<uint32_t*>(&a);
                o[2 * h + 1] = *reinterpret_cast<uint32_t*>(&c);
            }
        }
        stg_cs16(reinterpret_cast<uint4*>(g_w16) + i,
                 make_uint4(o[0], o[1], o[2], o[3]));
    }
}

// ---------------------------------------------------------------------------
// GEMM: out[M,N] = X16[M,K] @ W16[N,K]^T
// CTA 128x128, 4 warps (2M x 2N), warp tile 64x64, BK=64, 3 stages,
// 2 CTAs/SM. Stage offsets are compile-time immediates. Prefetch split into
// two homogeneous 8-clumps: A-half after k0, B-half (+commit) after k2.
// ---------------------------------------------------------------------------
__global__ void __launch_bounds__(128, 2) qlinear_gemm(
    const float* __restrict__ scale_w,
    const float* __restrict__ bias,
    float* __restrict__ out)
{
    extern __shared__ char smem[];
    const uint32_t sbase = smem_u32(smem);
    const int tid = threadIdx.x;
    const int wid = tid >> 5;
    const int lane = tid & 31;
    const int wm = wid & 1;              // 2 warps along M (64 rows each)
    const int wn = wid >> 1;             // 2 warps along N (64 cols each)

    // Grouped rasterization: 16 M-tiles per group (L2 reuse).
    const int tiles_n = N_TOTAL / BN;    // 128
    const int GH = 16;
    const int bid = blockIdx.x;
    const int group = bid / (GH * tiles_n);
    const int rem = bid % (GH * tiles_n);
    const int tile_m = group * GH + (rem % GH);
    const int tile_n = rem / GH;

    // ---- loop-invariant cp.async addressing ----
    const int c_row = tid >> 3;          // 0..15
    const int c_seg = tid & 7;           // 0..7
    const uint32_t dstA = sbase + SWZ128((uint32_t)(c_row * 128 + c_seg * 16));
    const __half* srcA = g_x16 + (size_t)(tile_m * BM + c_row) * K_TOTAL + c_seg * 8;
    const __half* srcB = g_w16 + (size_t)(tile_n * BN + c_row) * K_TOTAL + c_seg * 8;

    // half-chunk loaders (stage offset is a compile-time immediate)
    auto load_A = [&](uint32_t stage_off) {
#pragma unroll
        for (int it = 0; it < 8; it++)
            cp_async16(dstA + stage_off + it * 2048,
                       srcA + (size_t)it * 16 * K_TOTAL);
        srcA += BK;
    };
    auto load_B = [&](uint32_t stage_off) {
#pragma unroll
        for (int it = 0; it < 8; it++)
            cp_async16(dstA + stage_off + A_BYTES + it * 2048,
                       srcB + (size_t)it * 16 * K_TOTAL);
        srcB += BK;
    };

    // ---- loop-invariant ldmatrix absolute addresses (stage 0) ----
    const int lrow = lane & 15;
    const int lcol = (lane >> 4) << 4;   // 0 or 16 bytes
    uint32_t absA[4], absB[4];
#pragma unroll
    for (int i = 0; i < 4; i++) {
        absA[i] = sbase + SWZ128((uint32_t)((wm * 64 + i * 16 + lrow) * 128 + lcol));
        absB[i] = sbase + SWZ128((uint32_t)((wn * 64 + i * 16 + lrow) * 128 + lcol))
                  + A_BYTES;
    }

    float acc[4][8][4];
#pragma unroll
    for (int i = 0; i < 4; i++)
#pragma unroll
        for (int j = 0; j < 8; j++)
#pragma unroll
            for (int v = 0; v < 4; v++) acc[i][j][v] = 0.f;

    // prologue: fill stages 0,1
    load_A(0);           load_B(0);           CP_COMMIT();
    load_A(STAGE_BYTES); load_B(STAGE_BYTES); CP_COMMIT();

    // one k16 step: ldsm + 32 MMA (homogeneous blocks)
    auto kstep = [&](uint32_t cur_off, int t) {
        const uint32_t tx = (uint32_t)(t << 5);
        uint32_t a[4][4];
        uint32_t b[8][2];
#pragma unroll
        for (int i = 0; i < 4; i++)
            ldsm_x4(a[i][0], a[i][1], a[i][2], a[i][3],
                    (absA[i] + cur_off) ^ tx);
#pragma unroll
        for (int jj = 0; jj < 4; jj++) {
            uint32_t r0, r1, r2, r3;
            ldsm_x4(r0, r1, r2, r3, (absB[jj] + cur_off) ^ tx);
            b[2 * jj][0] = r0;     b[2 * jj][1] = r2;
            b[2 * jj + 1][0] = r1; b[2 * jj + 1][1] = r3;
        }
#pragma unroll
        for (int i = 0; i < 4; i++)
#pragma unroll
            for (int j = 0; j < 8; j++)
                mma16816(acc[i][j], a[i], b[j]);
    };

    // chunk body: k0 -> A-clump -> k1 -> k2 -> B-clump+commit -> k3.
    // Prefetch targets stage (c+2)%3 != cur -> no hazard; commit still lands
    // a full chunk ahead of its consuming CP_WAIT.
    auto chunk_body = [&](uint32_t cur_off, uint32_t pre_off) {
        CP_WAIT(1);
        __syncthreads();
        kstep(cur_off, 0);
        load_A(pre_off);                 // unconditional (scratch is padded)
        kstep(cur_off, 1);
        kstep(cur_off, 2);
        load_B(pre_off);
        CP_COMMIT();
        kstep(cur_off, 3);
    };

    // 63 chunks in groups of 3 (stage offsets are literals), then 1 tail.
    for (int cc = 0; cc < NCHUNK - 1; cc += 3) {
        chunk_body(0u,               2u * STAGE_BYTES);
        chunk_body(STAGE_BYTES,      0u);
        chunk_body(2u * STAGE_BYTES, STAGE_BYTES);
    }
    chunk_body(0u, 2u * STAGE_BYTES);    // chunk 63 (63 % 3 == 0 -> stage 0)

    // ------------------------- Epilogue -----------------------------------
    // d frag: c0=(m=g, n=2u), c1=(g, 2u+1), c2=(g+8, 2u), c3=(g+8, 2u+1)
    const int g = lane >> 2;
    const int u = lane & 3;
#pragma unroll
    for (int i = 0; i < 4; i++) {
        int row0 = tile_m * BM + wm * 64 + i * 16 + g;
#pragma unroll
        for (int j = 0; j < 8; j++) {
            int col = tile_n * BN + wn * 64 + j * 8 + 2 * u;
            float2 sc = *(const float2*)(scale_w + col);
            float2 bi = *(const float2*)(bias + col);
            float2 y0 = make_float2(acc[i][j][0] * sc.x + bi.x,
                                    acc[i][j][1] * sc.y + bi.y);
            float2 y1 = make_float2(acc[i][j][2] * sc.x + bi.x,
                                    acc[i][j][3] * sc.y + bi.y);
            *(float2*)(out + (size_t)row0 * N_TOTAL + col) = y0;
            *(float2*)(out + (size_t)(row0 + 8) * N_TOTAL + col) = y1;
        }
    }
}

// ---------------------------------------------------------------------------
// kernel_launch
// ---------------------------------------------------------------------------
extern "C" void kernel_launch(void* const* d_in, const int* in_sizes, int n_in,
                              void* d_out, int out_size) {
    const float* x = (const float*)d_in[0];
    const void* wq = d_in[1];
    const float* scale = (const float*)d_in[2];
    const float* bias = (const float*)d_in[3];
    float* out = (float*)d_out;

    detect_w_kernel<<<1, 256>>>((const int4*)wq);
    cvt_all_kernel<<<XB + WB, 256>>>((const float4*)x, wq);

    cudaFuncSetAttribute(qlinear_gemm,
                         cudaFuncAttributeMaxDynamicSharedMemorySize, SMEM_GEMM);
    const int grid = (M_TOTAL / BM) * (N_TOTAL / BN);   // 8192
    qlinear_gemm<<<grid, 128, SMEM_GEMM>>>(scale, bias, out);
}

// round 14
// speedup vs baseline: 1.6671x; 1.0008x over previous
#include <cuda_runtime.h>
#include <cuda_fp16.h>
#include <cstdint>

// ---------------------------------------------------------------------------
// Problem constants
// ---------------------------------------------------------------------------
#define M_TOTAL 8192
#define N_TOTAL 16384
#define K_TOTAL 4096

#define BM 128
#define BN 128
#define BK 64                          // fp16 elems per K chunk (128 B rows)
#define NCHUNK (K_TOTAL / BK)          // 64
#define STAGES 3
#define A_BYTES 16384u                 // 128 rows * 128 B
#define STAGE_BYTES (2u * A_BYTES)     // A + B = 32768
#define SMEM_GEMM (STAGES * STAGE_BYTES)       // 98304 -> 2 CTAs/SM

// fp16 staging buffers (allocation-free scratch). Padded by one K-row so the
// unconditional tail prefetch (up to 2 chunks past K) stays in-bounds.
__device__ __half g_x16[(size_t)M_TOTAL * K_TOTAL + K_TOTAL];   // 64 MB + pad
__device__ __half g_w16[(size_t)N_TOTAL * K_TOTAL + K_TOTAL];   // 128 MB + pad
__device__ int g_w_is_i32;             // weight dtype flag (detect kernel)

// ---------------------------------------------------------------------------
// Helpers
// ---------------------------------------------------------------------------
__device__ __forceinline__ uint32_t smem_u32(const void* p) {
    uint32_t r;
    asm("{ .reg .u64 t; cvta.to.shared.u64 t, %1; cvt.u32.u64 %0, t; }"
        : "=r"(r) : "l"(p));
    return r;
}

// Classic 128-byte-row swizzle: bits[6:4] ^= bits[9:7]. XOR-linear.
#define SWZ128(o) ((o) ^ (((o) >> 3) & 0x70))

__device__ __forceinline__ void cp_async16(uint32_t dst, const void* src) {
    asm volatile("cp.async.cg.shared.global [%0], [%1], 16;\n"
                 :: "r"(dst), "l"(src));
}
#define CP_COMMIT() asm volatile("cp.async.commit_group;\n" ::: "memory")
#define CP_WAIT(n)  asm volatile("cp.async.wait_group %0;\n" :: "n"(n) : "memory")

__device__ __forceinline__ void ldsm_x4(uint32_t& r0, uint32_t& r1,
                                        uint32_t& r2, uint32_t& r3,
                                        uint32_t addr) {
    asm volatile("ldmatrix.sync.aligned.m8n8.x4.shared.b16 {%0,%1,%2,%3}, [%4];"
                 : "=r"(r0), "=r"(r1), "=r"(r2), "=r"(r3) : "r"(addr));
}

__device__ __forceinline__ void mma16816(float* d, const uint32_t* a,
                                         const uint32_t* b) {
    asm volatile(
        "mma.sync.aligned.m16n8k16.row.col.f32.f16.f16.f32 "
        "{%0,%1,%2,%3}, {%4,%5,%6,%7}, {%8,%9}, {%0,%1,%2,%3};"
        : "+f"(d[0]), "+f"(d[1]), "+f"(d[2]), "+f"(d[3])
        : "r"(a[0]), "r"(a[1]), "r"(a[2]), "r"(a[3]), "r"(b[0]), "r"(b[1]));
}

// Streaming (no-reuse) load/store for convert + epilogue traffic.
__device__ __forceinline__ uint4 ldg_cs16(const void* p) {
    uint4 v;
    asm volatile("ld.global.cs.v4.u32 {%0,%1,%2,%3}, [%4];"
                 : "=r"(v.x), "=r"(v.y), "=r"(v.z), "=r"(v.w) : "l"(p));
    return v;
}
__device__ __forceinline__ void stg_cs16(void* p, uint4 v) {
    asm volatile("st.global.cs.v4.u32 [%0], {%1,%2,%3,%4};"
                 :: "l"(p), "r"(v.x), "r"(v.y), "r"(v.z), "r"(v.w));
}
__device__ __forceinline__ void stg_cs8f(void* p, float x, float y) {
    asm volatile("st.global.cs.v2.f32 [%0], {%1,%2};"
                 :: "l"(p), "f"(x), "f"(y));
}

// ---------------------------------------------------------------------------
// Weight dtype detection. int8 bytes misread as int32 words land in
// [-127,127] with prob ~1.5e-5/word; 1024 words all in range => int32
// (false-positive prob ~(1.5e-5)^1024 ~ 0). One 4KB load round: ~1.5us.
// ---------------------------------------------------------------------------
__global__ void __launch_bounds__(256) detect_w_kernel(const int4* __restrict__ w) {
    __shared__ int s_out_of_range;
    if (threadIdx.x == 0) s_out_of_range = 0;
    __syncthreads();
    int4 v = w[threadIdx.x];
    int bad = (v.x < -127 || v.x > 127 || v.y < -127 || v.y > 127 ||
               v.z < -127 || v.z > 127 || v.w < -127 || v.w > 127);
    if (bad) atomicOr(&s_out_of_range, 1);
    __syncthreads();
    if (threadIdx.x == 0) g_w_is_i32 = s_out_of_range ? 0 : 1;
}

// ---------------------------------------------------------------------------
// Fused conversion kernel: blocks [0, XB) convert x (fp32->fp16, 4/thread);
// blocks [XB, XB+WB) convert weights (int->fp16 exact, 8/thread).
// All traffic uses .cs streaming hints (zero reuse; keep L2 clean).
// ---------------------------------------------------------------------------
#define XB ((int)((size_t)M_TOTAL * K_TOTAL / 4 / 256))        // 8192
#define WB ((int)((size_t)N_TOTAL * K_TOTAL / 8 / 256))        // 32768

__global__ void __launch_bounds__(256) cvt_all_kernel(
    const float4* __restrict__ x, const void* __restrict__ wraw) {
    int b = blockIdx.x;
    if (b < XB) {
        size_t i = (size_t)b * 256 + threadIdx.x;
        uint4 raw = ldg_cs16(x + i);
        float4 v = *reinterpret_cast<float4*>(&raw);
        __half2 a = __floats2half2_rn(v.x, v.y);
        __half2 c = __floats2half2_rn(v.z, v.w);
        uint2 o = make_uint2(*reinterpret_cast<uint32_t*>(&a),
                             *reinterpret_cast<uint32_t*>(&c));
        asm volatile("st.global.cs.v2.u32 [%0], {%1,%2};"
                     :: "l"(reinterpret_cast<uint2*>(g_x16) + i),
                        "r"(o.x), "r"(o.y));
    } else {
        size_t i = (size_t)(b - XB) * 256 + threadIdx.x;
        uint32_t o[4];
        if (g_w_is_i32) {
            const int4* w = (const int4*)wraw;
            uint4 r0 = ldg_cs16(w + 2 * i);
            uint4 r1 = ldg_cs16(w + 2 * i + 1);
            int4 v0 = *reinterpret_cast<int4*>(&r0);
            int4 v1 = *reinterpret_cast<int4*>(&r1);
            __half2 h0 = __floats2half2_rn((float)v0.x, (float)v0.y);
            __half2 h1 = __floats2half2_rn((float)v0.z, (float)v0.w);
            __half2 h2 = __floats2half2_rn((float)v1.x, (float)v1.y);
            __half2 h3 = __floats2half2_rn((float)v1.z, (float)v1.w);
            o[0] = *reinterpret_cast<uint32_t*>(&h0);
            o[1] = *reinterpret_cast<uint32_t*>(&h1);
            o[2] = *reinterpret_cast<uint32_t*>(&h2);
            o[3] = *reinterpret_cast<uint32_t*>(&h3);
        } else {
            const uint2* w = (const uint2*)wraw;
            uint2 r = w[i];
#pragma unroll
            for (int h = 0; h < 2; h++) {
                uint32_t v = h ? r.y : r.x;
                __half2 a = __floats2half2_rn((float)(int8_t)(v),
                                              (float)(int8_t)(v >> 8));
                __half2 c = __floats2half2_rn((float)(int8_t)(v >> 16),
                                              (float)(int8_t)(v >> 24));
                o[2 * h]     = *reinterpret_cast<uint32_t*>(&a);
                o[2 * h + 1] = *reinterpret_cast<uint32_t*>(&c);
            }
        }
        stg_cs16(reinterpret_cast<uint4*>(g_w16) + i,
                 make_uint4(o[0], o[1], o[2], o[3]));
    }
}

// ---------------------------------------------------------------------------
// GEMM: out[M,N] = X16[M,K] @ W16[N,K]^T
// CTA 128x128, 4 warps (2M x 2N), warp tile 64x64, BK=64, 3 stages,
// 2 CTAs/SM. Stage offsets are compile-time immediates. Prefetch split into
// two homogeneous 8-clumps: A-half after k0, B-half (+commit) after k2.
// (Pinned structure — R7/R11/R12 lineage; do not reorder.)
// ---------------------------------------------------------------------------
__global__ void __launch_bounds__(128, 2) qlinear_gemm(
    const float* __restrict__ scale_w,
    const float* __restrict__ bias,
    float* __restrict__ out)
{
    extern __shared__ char smem[];
    const uint32_t sbase = smem_u32(smem);
    const int tid = threadIdx.x;
    const int wid = tid >> 5;
    const int lane = tid & 31;
    const int wm = wid & 1;              // 2 warps along M (64 rows each)
    const int wn = wid >> 1;             // 2 warps along N (64 cols each)

    // Grouped rasterization: 16 M-tiles per group (L2 reuse).
    const int tiles_n = N_TOTAL / BN;    // 128
    const int GH = 16;
    const int bid = blockIdx.x;
    const int group = bid / (GH * tiles_n);
    const int rem = bid % (GH * tiles_n);
    const int tile_m = group * GH + (rem % GH);
    const int tile_n = rem / GH;

    // ---- loop-invariant cp.async addressing ----
    const int c_row = tid >> 3;          // 0..15
    const int c_seg = tid & 7;           // 0..7
    const uint32_t dstA = sbase + SWZ128((uint32_t)(c_row * 128 + c_seg * 16));
    const __half* srcA = g_x16 + (size_t)(tile_m * BM + c_row) * K_TOTAL + c_seg * 8;
    const __half* srcB = g_w16 + (size_t)(tile_n * BN + c_row) * K_TOTAL + c_seg * 8;

    // half-chunk loaders (stage offset is a compile-time immediate)
    auto load_A = [&](uint32_t stage_off) {
#pragma unroll
        for (int it = 0; it < 8; it++)
            cp_async16(dstA + stage_off + it * 2048,
                       srcA + (size_t)it * 16 * K_TOTAL);
        srcA += BK;
    };
    auto load_B = [&](uint32_t stage_off) {
#pragma unroll
        for (int it = 0; it < 8; it++)
            cp_async16(dstA + stage_off + A_BYTES + it * 2048,
                       srcB + (size_t)it * 16 * K_TOTAL);
        srcB += BK;
    };

    // ---- loop-invariant ldmatrix absolute addresses (stage 0) ----
    const int lrow = lane & 15;
    const int lcol = (lane >> 4) << 4;   // 0 or 16 bytes
    uint32_t absA[4], absB[4];
#pragma unroll
    for (int i = 0; i < 4; i++) {
        absA[i] = sbase + SWZ128((uint32_t)((wm * 64 + i * 16 + lrow) * 128 + lcol));
        absB[i] = sbase + SWZ128((uint32_t)((wn * 64 + i * 16 + lrow) * 128 + lcol))
                  + A_BYTES;
    }

    float acc[4][8][4];
#pragma unroll
    for (int i = 0; i < 4; i++)
#pragma unroll
        for (int j = 0; j < 8; j++)
#pragma unroll
            for (int v = 0; v < 4; v++) acc[i][j][v] = 0.f;

    // prologue: fill stages 0,1
    load_A(0);           load_B(0);           CP_COMMIT();
    load_A(STAGE_BYTES); load_B(STAGE_BYTES); CP_COMMIT();

    // one k16 step: ldsm + 32 MMA (homogeneous blocks)
    auto kstep = [&](uint32_t cur_off, int t) {
        const uint32_t tx = (uint32_t)(t << 5);
        uint32_t a[4][4];
        uint32_t b[8][2];
#pragma unroll
        for (int i = 0; i < 4; i++)
            ldsm_x4(a[i][0], a[i][1], a[i][2], a[i][3],
                    (absA[i] + cur_off) ^ tx);
#pragma unroll
        for (int jj = 0; jj < 4; jj++) {
            uint32_t r0, r1, r2, r3;
            ldsm_x4(r0, r1, r2, r3, (absB[jj] + cur_off) ^ tx);
            b[2 * jj][0] = r0;     b[2 * jj][1] = r2;
            b[2 * jj + 1][0] = r1; b[2 * jj + 1][1] = r3;
        }
#pragma unroll
        for (int i = 0; i < 4; i++)
#pragma unroll
            for (int j = 0; j < 8; j++)
                mma16816(acc[i][j], a[i], b[j]);
    };

    // chunk body: k0 -> A-clump -> k1 -> k2 -> B-clump+commit -> k3.
    auto chunk_body = [&](uint32_t cur_off, uint32_t pre_off) {
        CP_WAIT(1);
        __syncthreads();
        kstep(cur_off, 0);
        load_A(pre_off);                 // unconditional (scratch is padded)
        kstep(cur_off, 1);
        kstep(cur_off, 2);
        load_B(pre_off);
        CP_COMMIT();
        kstep(cur_off, 3);
    };

    // 63 chunks in groups of 3 (stage offsets are literals), then 1 tail.
    for (int cc = 0; cc < NCHUNK - 1; cc += 3) {
        chunk_body(0u,               2u * STAGE_BYTES);
        chunk_body(STAGE_BYTES,      0u);
        chunk_body(2u * STAGE_BYTES, STAGE_BYTES);
    }
    chunk_body(0u, 2u * STAGE_BYTES);    // chunk 63 (63 % 3 == 0 -> stage 0)

    // ------------------------- Epilogue -----------------------------------
    // d frag: c0=(m=g, n=2u), c1=(g, 2u+1), c2=(g+8, 2u), c3=(g+8, 2u+1)
    // Output is never re-read: stream stores (.cs) keep L2 for A/B tiles.
    const int g = lane >> 2;
    const int u = lane & 3;
#pragma unroll
    for (int i = 0; i < 4; i++) {
        int row0 = tile_m * BM + wm * 64 + i * 16 + g;
#pragma unroll
        for (int j = 0; j < 8; j++) {
            int col = tile_n * BN + wn * 64 + j * 8 + 2 * u;
            float2 sc = *(const float2*)__builtin_assume_aligned(scale_w + col, 8);
            float2 bi = *(const float2*)__builtin_assume_aligned(bias + col, 8);
            stg_cs8f(out + (size_t)row0 * N_TOTAL + col,
                     acc[i][j][0] * sc.x + bi.x, acc[i][j][1] * sc.y + bi.y);
            stg_cs8f(out + (size_t)(row0 + 8) * N_TOTAL + col,
                     acc[i][j][2] * sc.x + bi.x, acc[i][j][3] * sc.y + bi.y);
        }
    }
}

// ---------------------------------------------------------------------------
// kernel_launch
// ---------------------------------------------------------------------------
extern "C" void kernel_launch(void* const* d_in, const int* in_sizes, int n_in,
                              void* d_out, int out_size) {
    const float* x = (const float*)d_in[0];
    const void* wq = d_in[1];
    const float* scale = (const float*)d_in[2];
    const float* bias = (const float*)d_in[3];
    float* out = (float*)d_out;

    detect_w_kernel<<<1, 256>>>((const int4*)wq);
    cvt_all_kernel<<<XB + WB, 256>>>((const float4*)x, wq);

    cudaFuncSetAttribute(qlinear_gemm,
                         cudaFuncAttributeMaxDynamicSharedMemorySize, SMEM_GEMM);
    const int grid = (M_TOTAL / BM) * (N_TOTAL / BN);   // 8192
    qlinear_gemm<<<grid, 128, SMEM_GEMM>>>(scale, bias, out);
}

// round 15
// speedup vs baseline: 1.6713x; 1.0025x over previous
#include <cuda_runtime.h>
#include <cuda_fp16.h>
#include <cstdint>

// ---------------------------------------------------------------------------
// Problem constants
// ---------------------------------------------------------------------------
#define M_TOTAL 8192
#define N_TOTAL 16384
#define K_TOTAL 4096

#define BM 128
#define BN 128
#define BK 64                          // fp16 elems per K chunk (128 B rows)
#define NCHUNK (K_TOTAL / BK)          // 64
#define STAGES 3
#define A_BYTES 16384u                 // 128 rows * 128 B
#define STAGE_BYTES (2u * A_BYTES)     // A + B = 32768
#define SMEM_GEMM (STAGES * STAGE_BYTES)       // 98304 -> 2 CTAs/SM

// fp16 staging buffers (allocation-free scratch). Padded by one K-row so the
// unconditional tail prefetch (up to 2 chunks past K) stays in-bounds.
__device__ __half g_x16[(size_t)M_TOTAL * K_TOTAL + K_TOTAL];   // 64 MB + pad
__device__ __half g_w16[(size_t)N_TOTAL * K_TOTAL + K_TOTAL];   // 128 MB + pad

// ---------------------------------------------------------------------------
// Helpers
// ---------------------------------------------------------------------------
__device__ __forceinline__ uint32_t smem_u32(const void* p) {
    uint32_t r;
    asm("{ .reg .u64 t; cvta.to.shared.u64 t, %1; cvt.u32.u64 %0, t; }"
        : "=r"(r) : "l"(p));
    return r;
}

// Classic 128-byte-row swizzle: bits[6:4] ^= bits[9:7]. XOR-linear.
#define SWZ128(o) ((o) ^ (((o) >> 3) & 0x70))

__device__ __forceinline__ void cp_async16(uint32_t dst, const void* src) {
    asm volatile("cp.async.cg.shared.global [%0], [%1], 16;\n"
                 :: "r"(dst), "l"(src));
}
#define CP_COMMIT() asm volatile("cp.async.commit_group;\n" ::: "memory")
#define CP_WAIT(n)  asm volatile("cp.async.wait_group %0;\n" :: "n"(n) : "memory")

__device__ __forceinline__ void ldsm_x4(uint32_t& r0, uint32_t& r1,
                                        uint32_t& r2, uint32_t& r3,
                                        uint32_t addr) {
    asm volatile("ldmatrix.sync.aligned.m8n8.x4.shared.b16 {%0,%1,%2,%3}, [%4];"
                 : "=r"(r0), "=r"(r1), "=r"(r2), "=r"(r3) : "r"(addr));
}

__device__ __forceinline__ void mma16816(float* d, const uint32_t* a,
                                         const uint32_t* b) {
    asm volatile(
        "mma.sync.aligned.m16n8k16.row.col.f32.f16.f16.f32 "
        "{%0,%1,%2,%3}, {%4,%5,%6,%7}, {%8,%9}, {%0,%1,%2,%3};"
        : "+f"(d[0]), "+f"(d[1]), "+f"(d[2]), "+f"(d[3])
        : "r"(a[0]), "r"(a[1]), "r"(a[2]), "r"(a[3]), "r"(b[0]), "r"(b[1]));
}

// Streaming (no-reuse) load/store for convert + epilogue traffic.
__device__ __forceinline__ uint4 ldg_cs16(const void* p) {
    uint4 v;
    asm volatile("ld.global.cs.v4.u32 {%0,%1,%2,%3}, [%4];"
                 : "=r"(v.x), "=r"(v.y), "=r"(v.z), "=r"(v.w) : "l"(p));
    return v;
}
__device__ __forceinline__ void stg_cs16(void* p, uint4 v) {
    asm volatile("st.global.cs.v4.u32 [%0], {%1,%2,%3,%4};"
                 :: "l"(p), "r"(v.x), "r"(v.y), "r"(v.z), "r"(v.w));
}
__device__ __forceinline__ void stg_cs8f(void* p, float x, float y) {
    asm volatile("st.global.cs.v2.f32 [%0], {%1,%2};"
                 :: "l"(p), "f"(x), "f"(y));
}

// ---------------------------------------------------------------------------
// Fused conversion kernel.
// Blocks [0, XB): x fp32->fp16, 8 elems/thread (two float4 -> one uint4).
// Blocks [XB, XB+WB): weights -> fp16 exact, 8 elems/thread.
//   Dtype is detected per-warp from the buffer's first 32 int32 words (one
//   L2-broadcast 128B line; __all_sync in-range vote). For int8 data the
//   vote fails with prob 1-(1.5e-5)^32 ~ 1, so the int32-view wide reads
//   (OOB on an int8 buffer) are never issued in that case. Warp-uniform,
//   deterministic, no extra DRAM traffic, no separate detect launch.
// All traffic uses .cs streaming hints (zero reuse; keep L2 clean).
// ---------------------------------------------------------------------------
#define XB ((int)((size_t)M_TOTAL * K_TOTAL / 8 / 256))        // 4096
#define WB ((int)((size_t)N_TOTAL * K_TOTAL / 8 / 256))        // 32768

__global__ void __launch_bounds__(256) cvt_all_kernel(
    const float4* __restrict__ x, const void* __restrict__ wraw) {
    int b = blockIdx.x;
    if (b < XB) {
        size_t i = (size_t)b * 256 + threadIdx.x;       // uint4 output index
        uint4 ra = ldg_cs16(x + 2 * i);
        uint4 rb = ldg_cs16(x + 2 * i + 1);
        float4 v0 = *reinterpret_cast<float4*>(&ra);
        float4 v1 = *reinterpret_cast<float4*>(&rb);
        __half2 h0 = __floats2half2_rn(v0.x, v0.y);
        __half2 h1 = __floats2half2_rn(v0.z, v0.w);
        __half2 h2 = __floats2half2_rn(v1.x, v1.y);
        __half2 h3 = __floats2half2_rn(v1.z, v1.w);
        stg_cs16(reinterpret_cast<uint4*>(g_x16) + i,
                 make_uint4(*reinterpret_cast<uint32_t*>(&h0),
                            *reinterpret_cast<uint32_t*>(&h1),
                            *reinterpret_cast<uint32_t*>(&h2),
                            *reinterpret_cast<uint32_t*>(&h3)));
    } else {
        size_t i = (size_t)(b - XB) * 256 + threadIdx.x;
        // Warp-local dtype probe: first 128B of the buffer (hot in L2).
        int probe = __ldg((const int*)wraw + (threadIdx.x & 31));
        bool is_i32 = __all_sync(0xFFFFFFFFu, probe >= -127 && probe <= 127);
        uint32_t o[4];
        if (is_i32) {
            const int4* w = (const int4*)wraw;
            uint4 r0 = ldg_cs16(w + 2 * i);
            uint4 r1 = ldg_cs16(w + 2 * i + 1);
            int4 v0 = *reinterpret_cast<int4*>(&r0);
            int4 v1 = *reinterpret_cast<int4*>(&r1);
            __half2 h0 = __floats2half2_rn((float)v0.x, (float)v0.y);
            __half2 h1 = __floats2half2_rn((float)v0.z, (float)v0.w);
            __half2 h2 = __floats2half2_rn((float)v1.x, (float)v1.y);
            __half2 h3 = __floats2half2_rn((float)v1.z, (float)v1.w);
            o[0] = *reinterpret_cast<uint32_t*>(&h0);
            o[1] = *reinterpret_cast<uint32_t*>(&h1);
            o[2] = *reinterpret_cast<uint32_t*>(&h2);
            o[3] = *reinterpret_cast<uint32_t*>(&h3);
        } else {
            const uint2* w = (const uint2*)wraw;
            uint2 r = w[i];
#pragma unroll
            for (int h = 0; h < 2; h++) {
                uint32_t v = h ? r.y : r.x;
                __half2 a = __floats2half2_rn((float)(int8_t)(v),
                                              (float)(int8_t)(v >> 8));
                __half2 c = __floats2half2_rn((float)(int8_t)(v >> 16),
                                              (float)(int8_t)(v >> 24));
                o[2 * h]     = *reinterpret_cast<uint32_t*>(&a);
                o[2 * h + 1] = *reinterpret_cast<uint32_t*>(&c);
            }
        }
        stg_cs16(reinterpret_cast<uint4*>(g_w16) + i,
                 make_uint4(o[0], o[1], o[2], o[3]));
    }
}

// ---------------------------------------------------------------------------
// GEMM: out[M,N] = X16[M,K] @ W16[N,K]^T
// CTA 128x128, 4 warps (2M x 2N), warp tile 64x64, BK=64, 3 stages,
// 2 CTAs/SM. Stage offsets are compile-time immediates. Prefetch split into
// two homogeneous 8-clumps: A-half after k0, B-half (+commit) after k2.
// (Pinned structure — R7/R11/R12/R13 lineage; do not reorder.)
// ---------------------------------------------------------------------------
__global__ void __launch_bounds__(128, 2) qlinear_gemm(
    const float* __restrict__ scale_w,
    const float* __restrict__ bias,
    float* __restrict__ out)
{
    extern __shared__ char smem[];
    const uint32_t sbase = smem_u32(smem);
    const int tid = threadIdx.x;
    const int wid = tid >> 5;
    const int lane = tid & 31;
    const int wm = wid & 1;              // 2 warps along M (64 rows each)
    const int wn = wid >> 1;             // 2 warps along N (64 cols each)

    // Grouped rasterization: 16 M-tiles per group (L2 reuse).
    const int tiles_n = N_TOTAL / BN;    // 128
    const int GH = 16;
    const int bid = blockIdx.x;
    const int group = bid / (GH * tiles_n);
    const int rem = bid % (GH * tiles_n);
    const int tile_m = group * GH + (rem % GH);
    const int tile_n = rem / GH;

    // ---- loop-invariant cp.async addressing ----
    const int c_row = tid >> 3;          // 0..15
    const int c_seg = tid & 7;           // 0..7
    const uint32_t dstA = sbase + SWZ128((uint32_t)(c_row * 128 + c_seg * 16));
    const __half* srcA = g_x16 + (size_t)(tile_m * BM + c_row) * K_TOTAL + c_seg * 8;
    const __half* srcB = g_w16 + (size_t)(tile_n * BN + c_row) * K_TOTAL + c_seg * 8;

    // half-chunk loaders (stage offset is a compile-time immediate)
    auto load_A = [&](uint32_t stage_off) {
#pragma unroll
        for (int it = 0; it < 8; it++)
            cp_async16(dstA + stage_off + it * 2048,
                       srcA + (size_t)it * 16 * K_TOTAL);
        srcA += BK;
    };
    auto load_B = [&](uint32_t stage_off) {
#pragma unroll
        for (int it = 0; it < 8; it++)
            cp_async16(dstA + stage_off + A_BYTES + it * 2048,
                       srcB + (size_t)it * 16 * K_TOTAL);
        srcB += BK;
    };

    // ---- loop-invariant ldmatrix absolute addresses (stage 0) ----
    const int lrow = lane & 15;
    const int lcol = (lane >> 4) << 4;   // 0 or 16 bytes
    uint32_t absA[4], absB[4];
#pragma unroll
    for (int i = 0; i < 4; i++) {
        absA[i] = sbase + SWZ128((uint32_t)((wm * 64 + i * 16 + lrow) * 128 + lcol));
        absB[i] = sbase + SWZ128((uint32_t)((wn * 64 + i * 16 + lrow) * 128 + lcol))
                  + A_BYTES;
    }

    float acc[4][8][4];
#pragma unroll
    for (int i = 0; i < 4; i++)
#pragma unroll
        for (int j = 0; j < 8; j++)
#pragma unroll
            for (int v = 0; v < 4; v++) acc[i][j][v] = 0.f;

    // prologue: fill stages 0,1
    load_A(0);           load_B(0);           CP_COMMIT();
    load_A(STAGE_BYTES); load_B(STAGE_BYTES); CP_COMMIT();

    // one k16 step: ldsm + 32 MMA (homogeneous blocks)
    auto kstep = [&](uint32_t cur_off, int t) {
        const uint32_t tx = (uint32_t)(t << 5);
        uint32_t a[4][4];
        uint32_t b[8][2];
#pragma unroll
        for (int i = 0; i < 4; i++)
            ldsm_x4(a[i][0], a[i][1], a[i][2], a[i][3],
                    (absA[i] + cur_off) ^ tx);
#pragma unroll
        for (int jj = 0; jj < 4; jj++) {
            uint32_t r0, r1, r2, r3;
            ldsm_x4(r0, r1, r2, r3, (absB[jj] + cur_off) ^ tx);
            b[2 * jj][0] = r0;     b[2 * jj][1] = r2;
            b[2 * jj + 1][0] = r1; b[2 * jj + 1][1] = r3;
        }
#pragma unroll
        for (int i = 0; i < 4; i++)
#pragma unroll
            for (int j = 0; j < 8; j++)
                mma16816(acc[i][j], a[i], b[j]);
    };

    // chunk body: k0 -> A-clump -> k1 -> k2 -> B-clump+commit -> k3.
    auto chunk_body = [&](uint32_t cur_off, uint32_t pre_off) {
        CP_WAIT(1);
        __syncthreads();
        kstep(cur_off, 0);
        load_A(pre_off);                 // unconditional (scratch is padded)
        kstep(cur_off, 1);
        kstep(cur_off, 2);
        load_B(pre_off);
        CP_COMMIT();
        kstep(cur_off, 3);
    };

    // 63 chunks in groups of 3 (stage offsets are literals), then 1 tail.
    for (int cc = 0; cc < NCHUNK - 1; cc += 3) {
        chunk_body(0u,               2u * STAGE_BYTES);
        chunk_body(STAGE_BYTES,      0u);
        chunk_body(2u * STAGE_BYTES, STAGE_BYTES);
    }
    chunk_body(0u, 2u * STAGE_BYTES);    // chunk 63 (63 % 3 == 0 -> stage 0)

    // ------------------------- Epilogue -----------------------------------
    // d frag: c0=(m=g, n=2u), c1=(g, 2u+1), c2=(g+8, 2u), c3=(g+8, 2u+1)
    // Output is never re-read: stream stores (.cs) keep L2 for A/B tiles.
    const int g = lane >> 2;
    const int u = lane & 3;
#pragma unroll
    for (int i = 0; i < 4; i++) {
        int row0 = tile_m * BM + wm * 64 + i * 16 + g;
#pragma unroll
        for (int j = 0; j < 8; j++) {
            int col = tile_n * BN + wn * 64 + j * 8 + 2 * u;
            float2 sc = *(const float2*)__builtin_assume_aligned(scale_w + col, 8);
            float2 bi = *(const float2*)__builtin_assume_aligned(bias + col, 8);
            stg_cs8f(out + (size_t)row0 * N_TOTAL + col,
                     acc[i][j][0] * sc.x + bi.x, acc[i][j][1] * sc.y + bi.y);
            stg_cs8f(out + (size_t)(row0 + 8) * N_TOTAL + col,
                     acc[i][j][2] * sc.x + bi.x, acc[i][j][3] * sc.y + bi.y);
        }
    }
}

// ---------------------------------------------------------------------------
// kernel_launch
// ---------------------------------------------------------------------------
extern "C" void kernel_launch(void* const* d_in, const int* in_sizes, int n_in,
                              void* d_out, int out_size) {
    const float* x = (const float*)d_in[0];
    const void* wq = d_in[1];
    const float* scale = (const float*)d_in[2];
    const float* bias = (const float*)d_in[3];
    float* out = (float*)d_out;

    cvt_all_kernel<<<XB + WB, 256>>>((const float4*)x, wq);

    cudaFuncSetAttribute(qlinear_gemm,
                         cudaFuncAttributeMaxDynamicSharedMemorySize, SMEM_GEMM);
    const int grid = (M_TOTAL / BM) * (N_TOTAL / BN);   // 8192
    qlinear_gemm<<<grid, 128, SMEM_GEMM>>>(scale, bias, out);
}

// round 16
// speedup vs baseline: 1.6731x; 1.0011x over previous
#include <cuda_runtime.h>
#include <cuda_fp16.h>
#include <cstdint>

// ---------------------------------------------------------------------------
// Problem constants
// ---------------------------------------------------------------------------
#define M_TOTAL 8192
#define N_TOTAL 16384
#define K_TOTAL 4096

#define BM 128
#define BN 128
#define BK 64                          // fp16 elems per K chunk (128 B rows)
#define NCHUNK (K_TOTAL / BK)          // 64
#define STAGES 3
#define A_BYTES 16384u                 // 128 rows * 128 B
#define STAGE_BYTES (2u * A_BYTES)     // A + B = 32768
#define SMEM_GEMM (STAGES * STAGE_BYTES)       // 98304 -> 2 CTAs/SM

// fp16 staging buffers (allocation-free scratch). Padded by one K-row so the
// unconditional tail prefetch (up to 2 chunks past K) stays in-bounds.
__device__ __half g_x16[(size_t)M_TOTAL * K_TOTAL + K_TOTAL];   // 64 MB + pad
__device__ __half g_w16[(size_t)N_TOTAL * K_TOTAL + K_TOTAL];   // 128 MB + pad

// ---------------------------------------------------------------------------
// Helpers
// ---------------------------------------------------------------------------
__device__ __forceinline__ uint32_t smem_u32(const void* p) {
    uint32_t r;
    asm("{ .reg .u64 t; cvta.to.shared.u64 t, %1; cvt.u32.u64 %0, t; }"
        : "=r"(r) : "l"(p));
    return r;
}

// Classic 128-byte-row swizzle: bits[6:4] ^= bits[9:7]. XOR-linear.
#define SWZ128(o) ((o) ^ (((o) >> 3) & 0x70))

__device__ __forceinline__ void cp_async16(uint32_t dst, const void* src) {
    asm volatile("cp.async.cg.shared.global [%0], [%1], 16;\n"
                 :: "r"(dst), "l"(src));
}
#define CP_COMMIT() asm volatile("cp.async.commit_group;\n" ::: "memory")
#define CP_WAIT(n)  asm volatile("cp.async.wait_group %0;\n" :: "n"(n) : "memory")

__device__ __forceinline__ void ldsm_x4(uint32_t& r0, uint32_t& r1,
                                        uint32_t& r2, uint32_t& r3,
                                        uint32_t addr) {
    asm volatile("ldmatrix.sync.aligned.m8n8.x4.shared.b16 {%0,%1,%2,%3}, [%4];"
                 : "=r"(r0), "=r"(r1), "=r"(r2), "=r"(r3) : "r"(addr));
}

__device__ __forceinline__ void mma16816(float* d, const uint32_t* a,
                                         const uint32_t* b) {
    asm volatile(
        "mma.sync.aligned.m16n8k16.row.col.f32.f16.f16.f32 "
        "{%0,%1,%2,%3}, {%4,%5,%6,%7}, {%8,%9}, {%0,%1,%2,%3};"
        : "+f"(d[0]), "+f"(d[1]), "+f"(d[2]), "+f"(d[3])
        : "r"(a[0]), "r"(a[1]), "r"(a[2]), "r"(a[3]), "r"(b[0]), "r"(b[1]));
}

// Streaming (no-reuse) load/store for convert + epilogue traffic.
__device__ __forceinline__ uint4 ldg_cs16(const void* p) {
    uint4 v;
    asm volatile("ld.global.cs.v4.u32 {%0,%1,%2,%3}, [%4];"
                 : "=r"(v.x), "=r"(v.y), "=r"(v.z), "=r"(v.w) : "l"(p));
    return v;
}
__device__ __forceinline__ void stg_cs16(void* p, uint4 v) {
    asm volatile("st.global.cs.v4.u32 [%0], {%1,%2,%3,%4};"
                 :: "l"(p), "r"(v.x), "r"(v.y), "r"(v.z), "r"(v.w));
}
__device__ __forceinline__ void stg_cs8f(void* p, float x, float y) {
    asm volatile("st.global.cs.v2.f32 [%0], {%1,%2};"
                 :: "l"(p), "f"(x), "f"(y));
}

// ---------------------------------------------------------------------------
// Fused conversion kernel.
// Blocks [0, XB): x fp32->fp16, 8 elems/thread (two float4 -> one uint4).
// Blocks [XB, XB+WB): weights -> fp16 exact, 8 elems/thread.
//   Dtype detected per-warp from the buffer's first 32 int32 words (one
//   L2-broadcast 128B line; __all_sync in-range vote). For int8 data the
//   vote fails with prob ~1, so the int32-view wide reads (OOB on an int8
//   buffer) are never issued in that case. Warp-uniform, deterministic.
// All traffic uses .cs streaming hints (zero reuse; keep L2 clean).
// ---------------------------------------------------------------------------
#define XB ((int)((size_t)M_TOTAL * K_TOTAL / 8 / 256))        // 4096
#define WB ((int)((size_t)N_TOTAL * K_TOTAL / 8 / 256))        // 32768

__global__ void __launch_bounds__(256) cvt_all_kernel(
    const float4* __restrict__ x, const void* __restrict__ wraw) {
    int b = blockIdx.x;
    if (b < XB) {
        size_t i = (size_t)b * 256 + threadIdx.x;       // uint4 output index
        uint4 ra = ldg_cs16(x + 2 * i);
        uint4 rb = ldg_cs16(x + 2 * i + 1);
        float4 v0 = *reinterpret_cast<float4*>(&ra);
        float4 v1 = *reinterpret_cast<float4*>(&rb);
        __half2 h0 = __floats2half2_rn(v0.x, v0.y);
        __half2 h1 = __floats2half2_rn(v0.z, v0.w);
        __half2 h2 = __floats2half2_rn(v1.x, v1.y);
        __half2 h3 = __floats2half2_rn(v1.z, v1.w);
        stg_cs16(reinterpret_cast<uint4*>(g_x16) + i,
                 make_uint4(*reinterpret_cast<uint32_t*>(&h0),
                            *reinterpret_cast<uint32_t*>(&h1),
                            *reinterpret_cast<uint32_t*>(&h2),
                            *reinterpret_cast<uint32_t*>(&h3)));
    } else {
        size_t i = (size_t)(b - XB) * 256 + threadIdx.x;
        // Warp-local dtype probe: first 128B of the buffer (hot in L2).
        int probe = __ldg((const int*)wraw + (threadIdx.x & 31));
        bool is_i32 = __all_sync(0xFFFFFFFFu, probe >= -127 && probe <= 127);
        uint32_t o[4];
        if (is_i32) {
            const int4* w = (const int4*)wraw;
            uint4 r0 = ldg_cs16(w + 2 * i);
            uint4 r1 = ldg_cs16(w + 2 * i + 1);
            int4 v0 = *reinterpret_cast<int4*>(&r0);
            int4 v1 = *reinterpret_cast<int4*>(&r1);
            __half2 h0 = __floats2half2_rn((float)v0.x, (float)v0.y);
            __half2 h1 = __floats2half2_rn((float)v0.z, (float)v0.w);
            __half2 h2 = __floats2half2_rn((float)v1.x, (float)v1.y);
            __half2 h3 = __floats2half2_rn((float)v1.z, (float)v1.w);
            o[0] = *reinterpret_cast<uint32_t*>(&h0);
            o[1] = *reinterpret_cast<uint32_t*>(&h1);
            o[2] = *reinterpret_cast<uint32_t*>(&h2);
            o[3] = *reinterpret_cast<uint32_t*>(&h3);
        } else {
            const uint2* w = (const uint2*)wraw;
            uint2 r = w[i];
#pragma unroll
            for (int h = 0; h < 2; h++) {
                uint32_t v = h ? r.y : r.x;
                __half2 a = __floats2half2_rn((float)(int8_t)(v),
                                              (float)(int8_t)(v >> 8));
                __half2 c = __floats2half2_rn((float)(int8_t)(v >> 16),
                                              (float)(int8_t)(v >> 24));
                o[2 * h]     = *reinterpret_cast<uint32_t*>(&a);
                o[2 * h + 1] = *reinterpret_cast<uint32_t*>(&c);
            }
        }
        stg_cs16(reinterpret_cast<uint4*>(g_w16) + i,
                 make_uint4(o[0], o[1], o[2], o[3]));
    }
}

// ---------------------------------------------------------------------------
// GEMM: out[M,N] = X16[M,K] @ W16[N,K]^T
// CTA 128x128, 4 warps (2M x 2N), warp tile 64x64, BK=64, 3 stages,
// 2 CTAs/SM. Stage offsets are compile-time immediates. Prefetch split into
// two homogeneous 8-clumps: A-half after k1, B-half (+commit) after k2 —
// keeps the post-barrier k0->k1 transition free of LDGSTS issue.
// (Pinned structure otherwise — R7/R11/R12/R13 lineage; do not reorder.)
// ---------------------------------------------------------------------------
__global__ void __launch_bounds__(128, 2) qlinear_gemm(
    const float* __restrict__ scale_w,
    const float* __restrict__ bias,
    float* __restrict__ out)
{
    extern __shared__ char smem[];
    const uint32_t sbase = smem_u32(smem);
    const int tid = threadIdx.x;
    const int wid = tid >> 5;
    const int lane = tid & 31;
    const int wm = wid & 1;              // 2 warps along M (64 rows each)
    const int wn = wid >> 1;             // 2 warps along N (64 cols each)

    // Grouped rasterization: 16 M-tiles per group (L2 reuse).
    const int tiles_n = N_TOTAL / BN;    // 128
    const int GH = 16;
    const int bid = blockIdx.x;
    const int group = bid / (GH * tiles_n);
    const int rem = bid % (GH * tiles_n);
    const int tile_m = group * GH + (rem % GH);
    const int tile_n = rem / GH;

    // ---- loop-invariant cp.async addressing ----
    const int c_row = tid >> 3;          // 0..15
    const int c_seg = tid & 7;           // 0..7
    const uint32_t dstA = sbase + SWZ128((uint32_t)(c_row * 128 + c_seg * 16));
    const __half* srcA = g_x16 + (size_t)(tile_m * BM + c_row) * K_TOTAL + c_seg * 8;
    const __half* srcB = g_w16 + (size_t)(tile_n * BN + c_row) * K_TOTAL + c_seg * 8;

    // half-chunk loaders (stage offset is a compile-time immediate)
    auto load_A = [&](uint32_t stage_off) {
#pragma unroll
        for (int it = 0; it < 8; it++)
            cp_async16(dstA + stage_off + it * 2048,
                       srcA + (size_t)it * 16 * K_TOTAL);
        srcA += BK;
    };
    auto load_B = [&](uint32_t stage_off) {
#pragma unroll
        for (int it = 0; it < 8; it++)
            cp_async16(dstA + stage_off + A_BYTES + it * 2048,
                       srcB + (size_t)it * 16 * K_TOTAL);
        srcB += BK;
    };

    // ---- loop-invariant ldmatrix absolute addresses (stage 0) ----
    const int lrow = lane & 15;
    const int lcol = (lane >> 4) << 4;   // 0 or 16 bytes
    uint32_t absA[4], absB[4];
#pragma unroll
    for (int i = 0; i < 4; i++) {
        absA[i] = sbase + SWZ128((uint32_t)((wm * 64 + i * 16 + lrow) * 128 + lcol));
        absB[i] = sbase + SWZ128((uint32_t)((wn * 64 + i * 16 + lrow) * 128 + lcol))
                  + A_BYTES;
    }

    float acc[4][8][4];
#pragma unroll
    for (int i = 0; i < 4; i++)
#pragma unroll
        for (int j = 0; j < 8; j++)
#pragma unroll
            for (int v = 0; v < 4; v++) acc[i][j][v] = 0.f;

    // prologue: fill stages 0,1
    load_A(0);           load_B(0);           CP_COMMIT();
    load_A(STAGE_BYTES); load_B(STAGE_BYTES); CP_COMMIT();

    // one k16 step: ldsm + 32 MMA (homogeneous blocks)
    auto kstep = [&](uint32_t cur_off, int t) {
        const uint32_t tx = (uint32_t)(t << 5);
        uint32_t a[4][4];
        uint32_t b[8][2];
#pragma unroll
        for (int i = 0; i < 4; i++)
            ldsm_x4(a[i][0], a[i][1], a[i][2], a[i][3],
                    (absA[i] + cur_off) ^ tx);
#pragma unroll
        for (int jj = 0; jj < 4; jj++) {
            uint32_t r0, r1, r2, r3;
            ldsm_x4(r0, r1, r2, r3, (absB[jj] + cur_off) ^ tx);
            b[2 * jj][0] = r0;     b[2 * jj][1] = r2;
            b[2 * jj + 1][0] = r1; b[2 * jj + 1][1] = r3;
        }
#pragma unroll
        for (int i = 0; i < 4; i++)
#pragma unroll
            for (int j = 0; j < 8; j++)
                mma16816(acc[i][j], a[i], b[j]);
    };

    // chunk body: k0 -> k1 -> A-clump -> k2 -> B-clump+commit -> k3.
    auto chunk_body = [&](uint32_t cur_off, uint32_t pre_off) {
        CP_WAIT(1);
        __syncthreads();
        kstep(cur_off, 0);
        kstep(cur_off, 1);
        load_A(pre_off);                 // unconditional (scratch is padded)
        kstep(cur_off, 2);
        load_B(pre_off);
        CP_COMMIT();
        kstep(cur_off, 3);
    };

    // 63 chunks in groups of 3 (stage offsets are literals), then 1 tail.
    for (int cc = 0; cc < NCHUNK - 1; cc += 3) {
        chunk_body(0u,               2u * STAGE_BYTES);
        chunk_body(STAGE_BYTES,      0u);
        chunk_body(2u * STAGE_BYTES, STAGE_BYTES);
    }
    chunk_body(0u, 2u * STAGE_BYTES);    // chunk 63 (63 % 3 == 0 -> stage 0)

    // ------------------------- Epilogue -----------------------------------
    // d frag: c0=(m=g, n=2u), c1=(g, 2u+1), c2=(g+8, 2u), c3=(g+8, 2u+1)
    // Output is never re-read: stream stores (.cs) keep L2 for A/B tiles.
    const int g = lane >> 2;
    const int u = lane & 3;
#pragma unroll
    for (int i = 0; i < 4; i++) {
        int row0 = tile_m * BM + wm * 64 + i * 16 + g;
#pragma unroll
        for (int j = 0; j < 8; j++) {
            int col = tile_n * BN + wn * 64 + j * 8 + 2 * u;
            float2 sc = *(const float2*)__builtin_assume_aligned(scale_w + col, 8);
            float2 bi = *(const float2*)__builtin_assume_aligned(bias + col, 8);
            stg_cs8f(out + (size_t)row0 * N_TOTAL + col,
                     acc[i][j][0] * sc.x + bi.x, acc[i][j][1] * sc.y + bi.y);
            stg_cs8f(out + (size_t)(row0 + 8) * N_TOTAL + col,
                     acc[i][j][2] * sc.x + bi.x, acc[i][j][3] * sc.y + bi.y);
        }
    }
}

// ---------------------------------------------------------------------------
// kernel_launch
// ---------------------------------------------------------------------------
extern "C" void kernel_launch(void* const* d_in, const int* in_sizes, int n_in,
                              void* d_out, int out_size) {
    const float* x = (const float*)d_in[0];
    const void* wq = d_in[1];
    const float* scale = (const float*)d_in[2];
    const float* bias = (const float*)d_in[3];
    float* out = (float*)d_out;

    cvt_all_kernel<<<XB + WB, 256>>>((const float4*)x, wq);

    cudaFuncSetAttribute(qlinear_gemm,
                         cudaFuncAttributeMaxDynamicSharedMemorySize, SMEM_GEMM);
    const int grid = (M_TOTAL / BM) * (N_TOTAL / BN);   // 8192
    qlinear_gemm<<<grid, 128, SMEM_GEMM>>>(scale, bias, out);
}

// round 17
// speedup vs baseline: 1.6776x; 1.0027x over previous
#include <cuda_runtime.h>
#include <cuda_fp16.h>
#include <cstdint>

// ---------------------------------------------------------------------------
// Problem constants
// ---------------------------------------------------------------------------
#define M_TOTAL 8192
#define N_TOTAL 16384
#define K_TOTAL 4096

#define BM 128
#define BN 128
#define BK 64                          // fp16 elems per K chunk (128 B rows)
#define NCHUNK (K_TOTAL / BK)          // 64
#define STAGES 3
#define A_BYTES 16384u                 // 128 rows * 128 B
#define STAGE_BYTES (2u * A_BYTES)     // A + B = 32768
#define SMEM_GEMM (STAGES * STAGE_BYTES)       // 98304 -> 2 CTAs/SM

// fp16 staging buffers (allocation-free scratch).
__device__ __half g_x16[(size_t)M_TOTAL * K_TOTAL + K_TOTAL];   // 64 MB + pad
__device__ __half g_w16[(size_t)N_TOTAL * K_TOTAL + K_TOTAL];   // 128 MB + pad

// ---------------------------------------------------------------------------
// Helpers
// ---------------------------------------------------------------------------
__device__ __forceinline__ uint32_t smem_u32(const void* p) {
    uint32_t r;
    asm("{ .reg .u64 t; cvta.to.shared.u64 t, %1; cvt.u32.u64 %0, t; }"
        : "=r"(r) : "l"(p));
    return r;
}

// Classic 128-byte-row swizzle: bits[6:4] ^= bits[9:7]. XOR-linear.
#define SWZ128(o) ((o) ^ (((o) >> 3) & 0x70))

__device__ __forceinline__ void cp_async16(uint32_t dst, const void* src) {
    asm volatile("cp.async.cg.shared.global [%0], [%1], 16;\n"
                 :: "r"(dst), "l"(src));
}
#define CP_COMMIT() asm volatile("cp.async.commit_group;\n" ::: "memory")
#define CP_WAIT(n)  asm volatile("cp.async.wait_group %0;\n" :: "n"(n) : "memory")

__device__ __forceinline__ void ldsm_x4(uint32_t& r0, uint32_t& r1,
                                        uint32_t& r2, uint32_t& r3,
                                        uint32_t addr) {
    asm volatile("ldmatrix.sync.aligned.m8n8.x4.shared.b16 {%0,%1,%2,%3}, [%4];"
                 : "=r"(r0), "=r"(r1), "=r"(r2), "=r"(r3) : "r"(addr));
}

__device__ __forceinline__ void mma16816(float* d, const uint32_t* a,
                                         const uint32_t* b) {
    asm volatile(
        "mma.sync.aligned.m16n8k16.row.col.f32.f16.f16.f32 "
        "{%0,%1,%2,%3}, {%4,%5,%6,%7}, {%8,%9}, {%0,%1,%2,%3};"
        : "+f"(d[0]), "+f"(d[1]), "+f"(d[2]), "+f"(d[3])
        : "r"(a[0]), "r"(a[1]), "r"(a[2]), "r"(a[3]), "r"(b[0]), "r"(b[1]));
}

// Streaming (no-reuse) load/store for convert + epilogue traffic.
__device__ __forceinline__ uint4 ldg_cs16(const void* p) {
    uint4 v;
    asm volatile("ld.global.cs.v4.u32 {%0,%1,%2,%3}, [%4];"
                 : "=r"(v.x), "=r"(v.y), "=r"(v.z), "=r"(v.w) : "l"(p));
    return v;
}
__device__ __forceinline__ void stg_cs16(void* p, uint4 v) {
    asm volatile("st.global.cs.v4.u32 [%0], {%1,%2,%3,%4};"
                 :: "l"(p), "r"(v.x), "r"(v.y), "r"(v.z), "r"(v.w));
}
__device__ __forceinline__ void stg_cs8f(void* p, float x, float y) {
    asm volatile("st.global.cs.v2.f32 [%0], {%1,%2};"
                 :: "l"(p), "f"(x), "f"(y));
}

// ---------------------------------------------------------------------------
// Fused conversion kernel.
// Blocks [0, XB): x fp32->fp16, 8 elems/thread (two float4 -> one uint4).
// Blocks [XB, XB+WB): weights -> fp16 exact, 8 elems/thread.
//   Dtype detected per-warp from the buffer's first 32 int32 words (one
//   L2-broadcast 128B line; __all_sync in-range vote). Warp-uniform,
//   deterministic, no extra launch.
// All traffic uses .cs streaming hints (zero reuse; keep L2 clean).
// ---------------------------------------------------------------------------
#define XB ((int)((size_t)M_TOTAL * K_TOTAL / 8 / 256))        // 4096
#define WB ((int)((size_t)N_TOTAL * K_TOTAL / 8 / 256))        // 32768

__global__ void __launch_bounds__(256) cvt_all_kernel(
    const float4* __restrict__ x, const void* __restrict__ wraw) {
    int b = blockIdx.x;
    if (b < XB) {
        size_t i = (size_t)b * 256 + threadIdx.x;       // uint4 output index
        uint4 ra = ldg_cs16(x + 2 * i);
        uint4 rb = ldg_cs16(x + 2 * i + 1);
        float4 v0 = *reinterpret_cast<float4*>(&ra);
        float4 v1 = *reinterpret_cast<float4*>(&rb);
        __half2 h0 = __floats2half2_rn(v0.x, v0.y);
        __half2 h1 = __floats2half2_rn(v0.z, v0.w);
        __half2 h2 = __floats2half2_rn(v1.x, v1.y);
        __half2 h3 = __floats2half2_rn(v1.z, v1.w);
        stg_cs16(reinterpret_cast<uint4*>(g_x16) + i,
                 make_uint4(*reinterpret_cast<uint32_t*>(&h0),
                            *reinterpret_cast<uint32_t*>(&h1),
                            *reinterpret_cast<uint32_t*>(&h2),
                            *reinterpret_cast<uint32_t*>(&h3)));
    } else {
        size_t i = (size_t)(b - XB) * 256 + threadIdx.x;
        // Warp-local dtype probe: first 128B of the buffer (hot in L2).
        int probe = __ldg((const int*)wraw + (threadIdx.x & 31));
        bool is_i32 = __all_sync(0xFFFFFFFFu, probe >= -127 && probe <= 127);
        uint32_t o[4];
        if (is_i32) {
            const int4* w = (const int4*)wraw;
            uint4 r0 = ldg_cs16(w + 2 * i);
            uint4 r1 = ldg_cs16(w + 2 * i + 1);
            int4 v0 = *reinterpret_cast<int4*>(&r0);
            int4 v1 = *reinterpret_cast<int4*>(&r1);
            __half2 h0 = __floats2half2_rn((float)v0.x, (float)v0.y);
            __half2 h1 = __floats2half2_rn((float)v0.z, (float)v0.w);
            __half2 h2 = __floats2half2_rn((float)v1.x, (float)v1.y);
            __half2 h3 = __floats2half2_rn((float)v1.z, (float)v1.w);
            o[0] = *reinterpret_cast<uint32_t*>(&h0);
            o[1] = *reinterpret_cast<uint32_t*>(&h1);
            o[2] = *reinterpret_cast<uint32_t*>(&h2);
            o[3] = *reinterpret_cast<uint32_t*>(&h3);
        } else {
            const uint2* w = (const uint2*)wraw;
            uint2 r = w[i];
#pragma unroll
            for (int h = 0; h < 2; h++) {
                uint32_t v = h ? r.y : r.x;
                __half2 a = __floats2half2_rn((float)(int8_t)(v),
                                              (float)(int8_t)(v >> 8));
                __half2 c = __floats2half2_rn((float)(int8_t)(v >> 16),
                                              (float)(int8_t)(v >> 24));
                o[2 * h]     = *reinterpret_cast<uint32_t*>(&a);
                o[2 * h + 1] = *reinterpret_cast<uint32_t*>(&c);
            }
        }
        stg_cs16(reinterpret_cast<uint4*>(g_w16) + i,
                 make_uint4(o[0], o[1], o[2], o[3]));
    }
}

// ---------------------------------------------------------------------------
// GEMM: out[M,N] = X16[M,K] @ W16[N,K]^T
// CTA 128x128, 4 warps (2M x 2N), warp tile 64x64, BK=64, 3 stages,
// 2 CTAs/SM. Stage offsets are compile-time immediates. Prefetch split into
// two homogeneous 8-clumps (A after k1, B+commit after k2). Tail peeled:
// chunks 62/63 issue NO prefetch (no garbage LDGSTS / DRAM traffic).
// (Pinned structure otherwise — R7/R11/R12/R13/R16 lineage; do not reorder.)
// ---------------------------------------------------------------------------
__global__ void __launch_bounds__(128, 2) qlinear_gemm(
    const float* __restrict__ scale_w,
    const float* __restrict__ bias,
    float* __restrict__ out)
{
    extern __shared__ char smem[];
    const uint32_t sbase = smem_u32(smem);
    const int tid = threadIdx.x;
    const int wid = tid >> 5;
    const int lane = tid & 31;
    const int wm = wid & 1;              // 2 warps along M (64 rows each)
    const int wn = wid >> 1;             // 2 warps along N (64 cols each)

    // Grouped rasterization: 16 M-tiles per group (L2 reuse).
    const int tiles_n = N_TOTAL / BN;    // 128
    const int GH = 16;
    const int bid = blockIdx.x;
    const int group = bid / (GH * tiles_n);
    const int rem = bid % (GH * tiles_n);
    const int tile_m = group * GH + (rem % GH);
    const int tile_n = rem / GH;

    // ---- loop-invariant cp.async addressing ----
    const int c_row = tid >> 3;          // 0..15
    const int c_seg = tid & 7;           // 0..7
    const uint32_t dstA = sbase + SWZ128((uint32_t)(c_row * 128 + c_seg * 16));
    const __half* srcA = g_x16 + (size_t)(tile_m * BM + c_row) * K_TOTAL + c_seg * 8;
    const __half* srcB = g_w16 + (size_t)(tile_n * BN + c_row) * K_TOTAL + c_seg * 8;

    // half-chunk loaders (stage offset is a compile-time immediate)
    auto load_A = [&](uint32_t stage_off) {
#pragma unroll
        for (int it = 0; it < 8; it++)
            cp_async16(dstA + stage_off + it * 2048,
                       srcA + (size_t)it * 16 * K_TOTAL);
        srcA += BK;
    };
    auto load_B = [&](uint32_t stage_off) {
#pragma unroll
        for (int it = 0; it < 8; it++)
            cp_async16(dstA + stage_off + A_BYTES + it * 2048,
                       srcB + (size_t)it * 16 * K_TOTAL);
        srcB += BK;
    };

    // ---- loop-invariant ldmatrix absolute addresses (stage 0) ----
    const int lrow = lane & 15;
    const int lcol = (lane >> 4) << 4;   // 0 or 16 bytes
    uint32_t absA[4], absB[4];
#pragma unroll
    for (int i = 0; i < 4; i++) {
        absA[i] = sbase + SWZ128((uint32_t)((wm * 64 + i * 16 + lrow) * 128 + lcol));
        absB[i] = sbase + SWZ128((uint32_t)((wn * 64 + i * 16 + lrow) * 128 + lcol))
                  + A_BYTES;
    }

    float acc[4][8][4];
#pragma unroll
    for (int i = 0; i < 4; i++)
#pragma unroll
        for (int j = 0; j < 8; j++)
#pragma unroll
            for (int v = 0; v < 4; v++) acc[i][j][v] = 0.f;

    // prologue: fill stages 0,1
    load_A(0);           load_B(0);           CP_COMMIT();
    load_A(STAGE_BYTES); load_B(STAGE_BYTES); CP_COMMIT();

    // one k16 step: ldsm + 32 MMA (homogeneous blocks)
    auto kstep = [&](uint32_t cur_off, int t) {
        const uint32_t tx = (uint32_t)(t << 5);
        uint32_t a[4][4];
        uint32_t b[8][2];
#pragma unroll
        for (int i = 0; i < 4; i++)
            ldsm_x4(a[i][0], a[i][1], a[i][2], a[i][3],
                    (absA[i] + cur_off) ^ tx);
#pragma unroll
        for (int jj = 0; jj < 4; jj++) {
            uint32_t r0, r1, r2, r3;
            ldsm_x4(r0, r1, r2, r3, (absB[jj] + cur_off) ^ tx);
            b[2 * jj][0] = r0;     b[2 * jj][1] = r2;
            b[2 * jj + 1][0] = r1; b[2 * jj + 1][1] = r3;
        }
#pragma unroll
        for (int i = 0; i < 4; i++)
#pragma unroll
            for (int j = 0; j < 8; j++)
                mma16816(acc[i][j], a[i], b[j]);
    };

    // chunk body: k0 -> k1 -> A-clump -> k2 -> B-clump+commit -> k3.
    auto chunk_body = [&](uint32_t cur_off, uint32_t pre_off) {
        CP_WAIT(1);
        __syncthreads();
        kstep(cur_off, 0);
        kstep(cur_off, 1);
        load_A(pre_off);
        kstep(cur_off, 2);
        load_B(pre_off);
        CP_COMMIT();
        kstep(cur_off, 3);
    };

    // Chunks 0..61: full body (prefetch always in-bounds: c+2 <= 63).
    for (int cc = 0; cc < 60; cc += 3) {
        chunk_body(0u,               2u * STAGE_BYTES);
        chunk_body(STAGE_BYTES,      0u);
        chunk_body(2u * STAGE_BYTES, STAGE_BYTES);
    }
    chunk_body(0u,          2u * STAGE_BYTES);   // chunk 60 (pf 62 -> stage 2)
    chunk_body(STAGE_BYTES, 0u);                 // chunk 61 (pf 63 -> stage 0)

    // Tail chunks 62, 63: no prefetch. Group accounting:
    //   at 62 two groups pending -> CP_WAIT(1); at 63 one -> CP_WAIT(0).
    {
        CP_WAIT(1);                              // chunk 62, stage 2
        __syncthreads();
        kstep(2u * STAGE_BYTES, 0); kstep(2u * STAGE_BYTES, 1);
        kstep(2u * STAGE_BYTES, 2); kstep(2u * STAGE_BYTES, 3);
        CP_WAIT(0);                              // chunk 63, stage 0
        __syncthreads();
        kstep(0u, 0); kstep(0u, 1); kstep(0u, 2); kstep(0u, 3);
    }

    // ------------------------- Epilogue -----------------------------------
    // d frag: c0=(m=g, n=2u), c1=(g, 2u+1), c2=(g+8, 2u), c3=(g+8, 2u+1)
    // Output is never re-read: stream stores (.cs) keep L2 for A/B tiles.
    const int g = lane >> 2;
    const int u = lane & 3;
#pragma unroll
    for (int i = 0; i < 4; i++) {
        int row0 = tile_m * BM + wm * 64 + i * 16 + g;
#pragma unroll
        for (int j = 0; j < 8; j++) {
            int col = tile_n * BN + wn * 64 + j * 8 + 2 * u;
            float2 sc = *(const float2*)__builtin_assume_aligned(scale_w + col, 8);
            float2 bi = *(const float2*)__builtin_assume_aligned(bias + col, 8);
            stg_cs8f(out + (size_t)row0 * N_TOTAL + col,
                     acc[i][j][0] * sc.x + bi.x, acc[i][j][1] * sc.y + bi.y);
            stg_cs8f(out + (size_t)(row0 + 8) * N_TOTAL + col,
                     acc[i][j][2] * sc.x + bi.x, acc[i][j][3] * sc.y + bi.y);
        }
    }
}

// ---------------------------------------------------------------------------
// kernel_launch
// ---------------------------------------------------------------------------
extern "C" void kernel_launch(void* const* d_in, const int* in_sizes, int n_in,
                              void* d_out, int out_size) {
    const float* x = (const float*)d_in[0];
    const void* wq = d_in[1];
    const float* scale = (const float*)d_in[2];
    const float* bias = (const float*)d_in[3];
    float* out = (float*)d_out;

    cvt_all_kernel<<<XB + WB, 256>>>((const float4*)x, wq);

    cudaFuncSetAttribute(qlinear_gemm,
                         cudaFuncAttributeMaxDynamicSharedMemorySize, SMEM_GEMM);
    const int grid = (M_TOTAL / BM) * (N_TOTAL / BN);   // 8192
    qlinear_gemm<<<grid, 128, SMEM_GEMM>>>(scale, bias, out);
}